// round 14
// baseline (speedup 1.0000x reference)
#include <cuda_runtime.h>
#include <cuda_bf16.h>
#include <math.h>
#include <stdint.h>

// ---------------- problem constants ----------------
#define NB      8
#define CIN     512
#define HH      64
#define WW      64
#define OC      512
#define NA      9
#define NANC    (HH*WW*NA)  // 36864
#define PRE_NMS 2000
#define POST_NMS 300
#define CAND_MAX 2048
#define CAND_RANK 2047
#define KTOT 4608           // 9 taps x 512 ic, R3 k-order
#define RS_PX 128           // rescore GEMM pixel tile

#define OFF_LOCS   0
#define OFF_SCORES (NB*NANC*4)
#define OFF_ROIS   (OFF_SCORES + NB*NANC*2)
#define OFF_IND    (OFF_ROIS + NB*POST_NMS*4)
#define OFF_ANC    (OFF_IND + NB*POST_NMS)

// ---------------- scratch ----------------
__device__ float g_h[NB*OC*HH*WW];
__device__ float g_score[NB*18*HH*WW];
__device__ float g_loc[NB*36*HH*WW];
__device__ float g_boxes[NB*NANC*4];
__device__ unsigned long long g_key[NB*NANC];
__device__ float g_selbox[NB*PRE_NMS*4];
__device__ unsigned long long g_keep0[NB*32];
__device__ unsigned long long g_mask[(size_t)NB*PRE_NMS*32];

// bf16 2-way splits (approx conv): x channel-last [s][n][y][x][ic], w [s][tap][oc][ic]
__device__ __align__(16) __nv_bfloat16 g_xs[(size_t)2*NB*64*64*512];
__device__ __align__(16) __nv_bfloat16 g_ws[(size_t)2*9*512*512];

// exact-rescore scratch
__device__ __align__(16) float g_wg[(size_t)KTOT*512];                 // [k][oc]
__device__ __align__(16) float g_gather[(size_t)NB*KTOT*CAND_MAX];    // [n][k][slot]
__device__ __align__(16) float g_hex[(size_t)NB*CAND_MAX*512];        // [n][slot][oc]
__device__ unsigned long long g_tcand[NB];
__device__ int g_npx[NB];
__device__ unsigned short g_plist[NB*4096];
__device__ short g_pixslot[NB*4096];

// ---------------- helpers ----------------
__device__ __forceinline__ uint32_t smem_u32(const void* p) {
    uint32_t a;
    asm("{ .reg .u64 t; cvta.to.shared.u64 t, %1; cvt.u32.u64 %0, t; }" : "=r"(a) : "l"(p));
    return a;
}
#define SWZ(o) ((o) ^ (((o) >> 3) & 0x70))

__device__ __forceinline__ void cp16(uint32_t dst, const void* src, int nbytes) {
    asm volatile("cp.async.cg.shared.global [%0], [%1], 16, %2;"
                 :: "r"(dst), "l"(src), "r"(nbytes) : "memory");
}
#define CP_COMMIT() asm volatile("cp.async.commit_group;" ::: "memory")

__device__ __forceinline__ void ldx4(uint32_t* r, uint32_t addr) {
    asm volatile("ldmatrix.sync.aligned.m8n8.x4.shared.b16 {%0,%1,%2,%3}, [%4];"
                 : "=r"(r[0]), "=r"(r[1]), "=r"(r[2]), "=r"(r[3]) : "r"(addr));
}
__device__ __forceinline__ void mma16816(float* d, const uint32_t* a, uint32_t b0, uint32_t b1) {
    asm volatile("mma.sync.aligned.m16n8k16.row.col.f32.bf16.bf16.f32 "
                 "{%0,%1,%2,%3}, {%4,%5,%6,%7}, {%8,%9}, {%0,%1,%2,%3};"
                 : "+f"(d[0]), "+f"(d[1]), "+f"(d[2]), "+f"(d[3])
                 : "r"(a[0]), "r"(a[1]), "r"(a[2]), "r"(a[3]), "r"(b0), "r"(b1));
}

// ================= prep: split w -> 2x bf16 =================
__global__ __launch_bounds__(512) void split_w_kernel(const float* __restrict__ w)
{
    const int oc = blockIdx.x, ic = threadIdx.x;
    const float* src = w + ((size_t)oc*CIN + ic)*9;
    const size_t ss = (size_t)9*512*512;
#pragma unroll
    for (int t = 0; t < 9; ++t) {
        float v = src[t];
        __nv_bfloat16 b0 = __float2bfloat16_rn(v);
        float r1 = v - __bfloat162float(b0);
        __nv_bfloat16 b1 = __float2bfloat16_rn(r1);
        size_t o = ((size_t)t*512 + oc)*512 + ic;
        g_ws[o] = b0; g_ws[o + ss] = b1;
    }
}

// ================= prep: weights in R3 k-order [k][oc] =================
__global__ __launch_bounds__(256) void prep_wg_kernel(const float* __restrict__ w)
{
    const int k = blockIdx.x;
    const int cc = k / 72, r = k % 72, ici = r / 9, tap = r % 9;
    const int ky = tap / 3, kx = tap % 3, ch = cc*8 + ici;
    for (int oc = threadIdx.x; oc < 512; oc += 256)
        g_wg[(size_t)k*512 + oc] = w[(((size_t)oc*512 + ch)*3 + ky)*3 + kx];
}

// ================= prep: split x -> 2x bf16 channel-last =================
__global__ __launch_bounds__(256) void split_x_kernel(const float* __restrict__ x)
{
    __shared__ float tile[64][65];
    const int c0 = blockIdx.x * 64, y = blockIdx.y, n = blockIdx.z;
    const int t = threadIdx.x;
    {
        int ic = t >> 2, xq = (t & 3) * 16;
        const float4* src = (const float4*)(x + (((size_t)n*CIN + c0 + ic)*64 + y)*64 + xq);
#pragma unroll
        for (int k = 0; k < 4; ++k) {
            float4 v = src[k];
            tile[ic][xq + 4*k + 0] = v.x; tile[ic][xq + 4*k + 1] = v.y;
            tile[ic][xq + 4*k + 2] = v.z; tile[ic][xq + 4*k + 3] = v.w;
        }
    }
    __syncthreads();
    const int xw = t >> 2, ic0 = (t & 3) * 16;
    __align__(16) __nv_bfloat16 o0[16], o1[16];
#pragma unroll
    for (int k = 0; k < 16; ++k) {
        float v = tile[ic0 + k][xw];
        o0[k] = __float2bfloat16_rn(v);
        float r1 = v - __bfloat162float(o0[k]);
        o1[k] = __float2bfloat16_rn(r1);
    }
    const size_t ss = (size_t)NB*64*64*512;
    size_t base = (((size_t)n*64 + y)*64 + xw)*512 + c0 + ic0;
    ((uint4*)(g_xs + base))[0]        = ((uint4*)o0)[0];
    ((uint4*)(g_xs + base))[1]        = ((uint4*)o0)[1];
    ((uint4*)(g_xs + base + ss))[0]   = ((uint4*)o1)[0];
    ((uint4*)(g_xs + base + ss))[1]   = ((uint4*)o1)[1];
}

// ================= K1: approx 3x3 conv via mma.sync bf16 (2-split, 3-product) =================
// CTA: 128 pixels x 64 oc. 8 warps (4 M x 2 N), warp tile 32x32.
// SMEM: 2 buf x 2 splits x (A 16KB + B 8KB) = 96 KB -> 2 CTAs/SM.
#define SMEM_MMA_TOTAL (2*2*16384 + 2*2*8192)

__global__ void __launch_bounds__(256, 2) conv3x3_mma_kernel(const float* __restrict__ bias)
{
    extern __shared__ char smem[];
    const uint32_t sb = smem_u32(smem);
    const int n = blockIdx.z, ntile = blockIdx.y, mtile = blockIdx.x;
    const int y0 = mtile * 2;
    const int tid = threadIdx.x, wid = tid >> 5, lane = tid & 31;
    const int wm = wid & 3, wn = wid >> 2;
    const uint32_t A0 = sb, B0 = sb + 4*16384;

    const int r = tid >> 1, hq = tid & 1;      // A loader: pixel row, 64B half
    const int rb = tid >> 2, qb = tid & 3;     // B loader: oc row, 32B quarter
    const size_t xs_ss = (size_t)NB*64*64*512;
    const size_t ws_ss = (size_t)9*512*512;

    float acc[2][2][8];
#pragma unroll
    for (int a = 0; a < 2; ++a)
#pragma unroll
        for (int b = 0; b < 2; ++b)
#pragma unroll
            for (int c = 0; c < 8; ++c) acc[a][b][c] = 0.f;

    auto issue = [&](int chunk, int buf) {
        const int tap = chunk >> 3, c0 = (chunk & 7) << 6;
        const int ky = tap / 3, kx = tap % 3;
        const int yi = y0 + (r >> 6) + ky - 1;
        const int xi = (r & 63) + kx - 1;
        const bool ok = ((unsigned)yi < 64u) && ((unsigned)xi < 64u);
        const int asz = ok ? 16 : 0;
        const size_t aoff = (((size_t)n*64 + (ok ? yi : 0))*64 + (ok ? xi : 0))*512 + c0 + hq*32;
        const uint32_t bo = (uint32_t)r*128 + (uint32_t)hq*64;
        const size_t boff = ((size_t)tap*512 + (size_t)(ntile*64 + rb))*512 + c0 + qb*16;
        const uint32_t bb = (uint32_t)rb*128 + (uint32_t)qb*32;
#pragma unroll
        for (int s = 0; s < 2; ++s) {
            const char* srcA = (const char*)(g_xs + s*xs_ss + aoff);
            uint32_t dA = A0 + (buf*2 + s)*16384;
            cp16(dA + SWZ(bo +  0), srcA +  0, asz);
            cp16(dA + SWZ(bo + 16), srcA + 16, asz);
            cp16(dA + SWZ(bo + 32), srcA + 32, asz);
            cp16(dA + SWZ(bo + 48), srcA + 48, asz);
            const char* srcB = (const char*)(g_ws + s*ws_ss + boff);
            uint32_t dB = B0 + (buf*2 + s)*8192;
            cp16(dB + SWZ(bb +  0), srcB +  0, 16);
            cp16(dB + SWZ(bb + 16), srcB + 16, 16);
        }
        CP_COMMIT();
    };

    const int g8 = lane >> 3, r8 = lane & 7;
    const int a_row = wm*32 + (g8 & 1)*8 + r8;      // + mt*16
    const int a_kb  = (g8 >> 1)*16;
    const int b_row = wn*32 + (g8 >> 1)*8 + r8;     // + nt*16
    const int b_kb  = (g8 & 1)*16;

    // 3 products: a0b0, a1b0, a0b1 (a1b1 dropped: ~2^-18 relative)
    const int SA[3] = {0, 1, 0};
    const int SB[3] = {0, 0, 1};

    issue(0, 0);

    for (int c = 0; c < 72; ++c) {
        const int buf = c & 1;
        if (c + 1 < 72) {
            issue(c + 1, buf ^ 1);
            asm volatile("cp.async.wait_group 1;" ::: "memory");
        } else {
            asm volatile("cp.async.wait_group 0;" ::: "memory");
        }
        __syncthreads();

        const uint32_t Ab = A0 + buf*2*16384;
        const uint32_t Bb = B0 + buf*2*8192;
#pragma unroll
        for (int ks = 0; ks < 4; ++ks) {
            uint32_t afr[2][2][4];
#pragma unroll
            for (int s = 0; s < 2; ++s)
#pragma unroll
                for (int mt = 0; mt < 2; ++mt)
                    ldx4(afr[s][mt], Ab + s*16384 +
                         (uint32_t)SWZ((a_row + mt*16)*128 + ks*32 + a_kb));
#pragma unroll
            for (int nt = 0; nt < 2; ++nt) {
                uint32_t bfr[2][4];
#pragma unroll
                for (int s = 0; s < 2; ++s)
                    ldx4(bfr[s], Bb + s*8192 +
                         (uint32_t)SWZ((b_row + nt*16)*128 + ks*32 + b_kb));
#pragma unroll
                for (int p = 0; p < 3; ++p) {
                    const int s = SA[p], t = SB[p];
#pragma unroll
                    for (int mt = 0; mt < 2; ++mt) {
                        mma16816(&acc[mt][nt][0], afr[s][mt], bfr[t][0], bfr[t][1]);
                        mma16816(&acc[mt][nt][4], afr[s][mt], bfr[t][2], bfr[t][3]);
                    }
                }
            }
        }
        __syncthreads();
    }

    // epilogue: bias + relu -> g_h [n][oc][y][x]
#pragma unroll
    for (int mt = 0; mt < 2; ++mt) {
        const int pix0 = mtile*128 + wm*32 + mt*16 + (lane >> 2);
#pragma unroll
        for (int nt = 0; nt < 2; ++nt) {
#pragma unroll
            for (int h8 = 0; h8 < 2; ++h8) {
                const int oc = ntile*64 + wn*32 + nt*16 + h8*8 + (lane & 3)*2;
                const float b0 = __ldg(bias + oc), b1 = __ldg(bias + oc + 1);
#pragma unroll
                for (int rr = 0; rr < 2; ++rr) {
                    const int pix = pix0 + rr*8;
                    const int y = pix >> 6, xw = pix & 63;
                    float v0 = acc[mt][nt][h8*4 + rr*2 + 0] + b0;
                    float v1 = acc[mt][nt][h8*4 + rr*2 + 1] + b1;
                    g_h[(((size_t)n*OC + oc    )*64 + y)*64 + xw] = fmaxf(v0, 0.f);
                    g_h[(((size_t)n*OC + oc + 1)*64 + y)*64 + xw] = fmaxf(v1, 0.f);
                }
            }
        }
    }
}

// ================= K2: approx 1x1 convs =================
__global__ __launch_bounds__(256) void conv1x1_kernel(
    const float* __restrict__ sw, const float* __restrict__ sb,
    const float* __restrict__ lw, const float* __restrict__ lb)
{
    const int n = blockIdx.y;
    const int y = blockIdx.x;
    const int tid = threadIdx.x;
    const int xcol = tid & 63;
    const int cg = tid >> 6;

    __shared__ float hs[64][64];
    __shared__ float wsc[56][64];

    float acc[14];
#pragma unroll
    for (int j = 0; j < 14; ++j) acc[j] = 0.f;

    for (int c0 = 0; c0 < CIN; c0 += 64) {
        for (int idx = tid; idx < 64*64; idx += 256) {
            int ic = idx >> 6, xx = idx & 63;
            hs[ic][xx] = g_h[(((size_t)n*OC + c0 + ic)*HH + y)*WW + xx];
        }
        for (int idx = tid; idx < 56*64; idx += 256) {
            int c = idx >> 6, ic = idx & 63;
            float v = 0.f;
            if (c < 18) v = sw[(size_t)c*CIN + c0 + ic];
            else if (c < 54) v = lw[(size_t)(c-18)*CIN + c0 + ic];
            wsc[c][ic] = v;
        }
        __syncthreads();
#pragma unroll 8
        for (int ic = 0; ic < 64; ++ic) {
            float xv = hs[ic][xcol];
#pragma unroll
            for (int j = 0; j < 14; ++j)
                acc[j] = fmaf(wsc[cg + 4*j][ic], xv, acc[j]);
        }
        __syncthreads();
    }
    int p = y * WW + xcol;
#pragma unroll
    for (int j = 0; j < 14; ++j) {
        int c = cg + 4*j;
        if (c < 18)       g_score[((size_t)n*18 + c)*4096 + p] = acc[j] + sb[c];
        else if (c < 54)  g_loc[((size_t)n*36 + (c-18))*4096 + p] = acc[j] + lb[c-18];
    }
}

// ================= K3: approx boxes / keys + full outputs =================
__global__ __launch_bounds__(256) void boxes_kernel(float* __restrict__ out)
{
    const int n = blockIdx.y;
    const int i = blockIdx.x * 256 + threadIdx.x;
    if (i >= NANC) return;
    const int a  = i % NA;
    const int p  = i / NA;
    const int xx = p % WW;
    const int yy = p / WW;

    float s0 = g_score[((size_t)n*18 + 2*a    )*4096 + p];
    float s1 = g_score[((size_t)n*18 + 2*a + 1)*4096 + p];
    out[OFF_SCORES + ((size_t)n*NANC + i)*2 + 0] = s0;
    out[OFF_SCORES + ((size_t)n*NANC + i)*2 + 1] = s1;

    float l0 = g_loc[((size_t)n*36 + a*4 + 0)*4096 + p];
    float l1 = g_loc[((size_t)n*36 + a*4 + 1)*4096 + p];
    float l2 = g_loc[((size_t)n*36 + a*4 + 2)*4096 + p];
    float l3 = g_loc[((size_t)n*36 + a*4 + 3)*4096 + p];
    out[OFF_LOCS + ((size_t)n*NANC + i)*4 + 0] = l0;
    out[OFF_LOCS + ((size_t)n*NANC + i)*4 + 1] = l1;
    out[OFF_LOCS + ((size_t)n*NANC + i)*4 + 2] = l2;
    out[OFF_LOCS + ((size_t)n*NANC + i)*4 + 3] = l3;

    const double ratios[3] = {0.5, 1.0, 2.0};
    const double scales[3] = {8.0, 16.0, 32.0};
    double hh = (16.0 * scales[a % 3]) * sqrt(ratios[a / 3]);
    double wd = (16.0 * scales[a % 3]) * sqrt(1.0 / ratios[a / 3]);
    float ab0 = (float)(8.0 - hh / 2.0);
    float ab1 = (float)(8.0 - wd / 2.0);
    float ab2 = (float)(8.0 + hh / 2.0);
    float ab3 = (float)(8.0 + wd / 2.0);
    float a0 = ab0 + (float)(yy * 16);
    float a1 = ab1 + (float)(xx * 16);
    float a2 = ab2 + (float)(yy * 16);
    float a3 = ab3 + (float)(xx * 16);
    if (n == 0) {
        out[OFF_ANC + (size_t)i*4 + 0] = a0;
        out[OFF_ANC + (size_t)i*4 + 1] = a1;
        out[OFF_ANC + (size_t)i*4 + 2] = a2;
        out[OFF_ANC + (size_t)i*4 + 3] = a3;
    }

    float ha = __fadd_rn(a2, -a0);
    float wa = __fadd_rn(a3, -a1);
    float cy = __fadd_rn(a0, __fmul_rn(0.5f, ha));
    float cx = __fadd_rn(a1, __fmul_rn(0.5f, wa));
    float cy2 = __fadd_rn(__fmul_rn(l0, ha), cy);
    float cx2 = __fadd_rn(__fmul_rn(l1, wa), cx);
    float h2 = __fmul_rn(expf(l2), ha);
    float w2 = __fmul_rn(expf(l3), wa);
    float b0 = __fadd_rn(cy2, -__fmul_rn(0.5f, h2));
    float b1 = __fadd_rn(cx2, -__fmul_rn(0.5f, w2));
    float b2 = __fadd_rn(cy2,  __fmul_rn(0.5f, h2));
    float b3 = __fadd_rn(cx2,  __fmul_rn(0.5f, w2));
    b0 = fminf(fmaxf(b0, 0.f), 1024.f);
    b1 = fminf(fmaxf(b1, 0.f), 1024.f);
    b2 = fminf(fmaxf(b2, 0.f), 1024.f);
    b3 = fminf(fmaxf(b3, 0.f), 1024.f);
    bool valid = ((b2 - b0) >= 16.f) && ((b3 - b1) >= 16.f);

    float m = fmaxf(s0, s1);
    float e0 = expf(s0 - m), e1 = expf(s1 - m);
    float fg = e1 / (e0 + e1);
    if (!valid) fg = -INFINITY;

    float* bp = g_boxes + ((size_t)n*NANC + i)*4;
    bp[0] = b0; bp[1] = b1; bp[2] = b2; bp[3] = b3;

    unsigned int kb = __float_as_uint(fg);
    unsigned int k  = (kb & 0x80000000u) ? ~kb : (kb | 0x80000000u);
    g_key[(size_t)n*NANC + i] =
        ((unsigned long long)k << 16) | (unsigned long long)(65535 - i);
}

// ================= K4: candidate selection (threshold + pixel compaction) =================
__global__ __launch_bounds__(1024) void cand_kernel()
{
    const int n = blockIdx.x;
    const int tid = threadIdx.x;
    const int lane = tid & 31, wid = tid >> 5;
    __shared__ unsigned int hist[256];
    __shared__ unsigned long long s_prefix;
    __shared__ int s_rank;
    __shared__ unsigned char flag[4096];
    __shared__ int wsum[32];

    const unsigned long long* key = g_key + (size_t)n * NANC;
    if (tid == 0) { s_prefix = 0ULL; s_rank = CAND_RANK; }
    __syncthreads();

    for (int d = 5; d >= 0; --d) {
        if (tid < 256) hist[tid] = 0u;
        __syncthreads();
        unsigned long long pref = s_prefix;
        int sh = (d + 1) * 8;
        for (int idx = tid; idx < NANC; idx += 1024) {
            unsigned long long k = key[idx];
            if ((k >> sh) == (pref >> sh))
                atomicAdd(&hist[(unsigned)(k >> (8*d)) & 255u], 1u);
        }
        __syncthreads();
        if (tid == 0) {
            int cum = 0, rank = s_rank;
            for (int v = 255; v >= 0; --v) {
                int c = (int)hist[v];
                if (cum + c > rank) {
                    s_prefix = pref | ((unsigned long long)(unsigned)v << (8*d));
                    s_rank = rank - cum;
                    break;
                }
                cum += c;
            }
        }
        __syncthreads();
    }
    const unsigned long long T = s_prefix;
    if (tid == 0) g_tcand[n] = T;

    for (int p = tid; p < 4096; p += 1024) flag[p] = 0;
    __syncthreads();
    for (int i = tid; i < NANC; i += 1024)
        if (key[i] >= T) flag[i / 9] = 1;
    __syncthreads();

    int have[4], cnt = 0;
#pragma unroll
    for (int j = 0; j < 4; ++j) { have[j] = flag[tid*4 + j]; cnt += have[j]; }
    int incl = cnt;
#pragma unroll
    for (int off = 1; off < 32; off <<= 1) {
        int v = __shfl_up_sync(0xffffffffu, incl, off);
        if (lane >= off) incl += v;
    }
    if (lane == 31) wsum[wid] = incl;
    __syncthreads();
    if (wid == 0) {
        int v = wsum[lane];
        int inc2 = v;
#pragma unroll
        for (int off = 1; off < 32; off <<= 1) {
            int u = __shfl_up_sync(0xffffffffu, inc2, off);
            if (lane >= off) inc2 += u;
        }
        wsum[lane] = inc2 - v;   // exclusive
    }
    __syncthreads();
    int base = wsum[wid] + (incl - cnt);
    int run = 0;
#pragma unroll
    for (int j = 0; j < 4; ++j) {
        int p = tid*4 + j;
        if (have[j]) {
            int s = base + run; run++;
            g_plist[n*4096 + s] = (unsigned short)p;
            g_pixslot[n*4096 + p] = (short)s;
        } else {
            g_pixslot[n*4096 + p] = -1;
        }
    }
    if (tid == 1023) g_npx[n] = base + cnt;
}

// ================= K5: gather candidate im2col x in R3 k-order [n][k][slot] =================
__global__ __launch_bounds__(256) void gather_kernel(const float* __restrict__ x)
{
    const int n = blockIdx.y, k = blockIdx.x;
    const int cc = k / 72, r = k % 72, ici = r / 9, tap = r % 9;
    const int ky = tap / 3, kx = tap % 3, ch = cc*8 + ici;
    const int npx = g_npx[n];
    int lim = (npx + RS_PX - 1) & ~(RS_PX - 1);
    if (lim > CAND_MAX) lim = CAND_MAX;
    for (int s = threadIdx.x; s < lim; s += 256) {
        float v = 0.f;
        if (s < npx) {
            int pix = g_plist[n*4096 + s];
            int y = pix >> 6, xx = pix & 63;
            int yi = y + ky - 1, xi = xx + kx - 1;
            if ((unsigned)yi < 64u && (unsigned)xi < 64u)
                v = x[(((size_t)n*512 + ch)*64 + yi)*64 + xi];
        }
        g_gather[((size_t)n*KTOT + k)*CAND_MAX + s] = v;
    }
}

// ================= K6: exact rescore GEMM — bit-exact R3 fmaf chains =================
// CTA: 128 px x 64 oc, 256 threads, 8x4 acc/thread. Sequential k 0..4607 per output.
// SMEM: 2 buf x (xs 16KB + ws 8KB) = 48KB -> 3 CTAs/SM.
__global__ void __launch_bounds__(256, 3) rescore_gemm_kernel(const float* __restrict__ bias)
{
    __shared__ float xs[2][32][128];
    __shared__ float ws[2][32][64];
    const int sblk = blockIdx.x, ob = blockIdx.y, n = blockIdx.z;
    if (sblk * RS_PX >= g_npx[n]) return;
    const int tid = threadIdx.x;
    const int pq = tid & 15, oq = tid >> 4;      // 16 px-groups of 8, 16 oc-groups of 4
    const size_t gbase = (size_t)n*KTOT*CAND_MAX + (size_t)sblk*RS_PX;

    float acc[8][4];
#pragma unroll
    for (int i = 0; i < 8; ++i)
#pragma unroll
        for (int j = 0; j < 4; ++j) acc[i][j] = 0.f;

    // preload kt=0
#pragma unroll
    for (int q = 0; q < 4; ++q) {
        int idx = tid + q*256, row = idx >> 5, c4 = idx & 31;
        *(float4*)&xs[0][row][c4*4] =
            *(const float4*)(g_gather + gbase + (size_t)row*CAND_MAX + c4*4);
    }
#pragma unroll
    for (int q = 0; q < 2; ++q) {
        int idx = tid + q*256, row = idx >> 4, c4 = idx & 15;
        *(float4*)&ws[0][row][c4*4] =
            *(const float4*)(g_wg + (size_t)row*512 + ob*64 + c4*4);
    }
    __syncthreads();
    int buf = 0;

    for (int kt = 0; kt < 144; ++kt) {
        float4 rx[4], rw[2];
        if (kt < 143) {
            const int k1 = (kt + 1) * 32;
#pragma unroll
            for (int q = 0; q < 4; ++q) {
                int idx = tid + q*256, row = idx >> 5, c4 = idx & 31;
                rx[q] = *(const float4*)(g_gather + gbase + (size_t)(k1 + row)*CAND_MAX + c4*4);
            }
#pragma unroll
            for (int q = 0; q < 2; ++q) {
                int idx = tid + q*256, row = idx >> 4, c4 = idx & 15;
                rw[q] = *(const float4*)(g_wg + (size_t)(k1 + row)*512 + ob*64 + c4*4);
            }
        }
#pragma unroll
        for (int kk = 0; kk < 32; ++kk) {
            float4 xv0 = *(float4*)&xs[buf][kk][pq*8];
            float4 xv1 = *(float4*)&xs[buf][kk][pq*8 + 4];
            float4 wv  = *(float4*)&ws[buf][kk][oq*4];
            float xa[8] = {xv0.x, xv0.y, xv0.z, xv0.w, xv1.x, xv1.y, xv1.z, xv1.w};
            float wa[4] = {wv.x, wv.y, wv.z, wv.w};
#pragma unroll
            for (int i = 0; i < 8; ++i)
#pragma unroll
                for (int j = 0; j < 4; ++j)
                    acc[i][j] = __fmaf_rn(wa[j], xa[i], acc[i][j]);
        }
        if (kt < 143) {
            __syncthreads();
#pragma unroll
            for (int q = 0; q < 4; ++q) {
                int idx = tid + q*256, row = idx >> 5, c4 = idx & 31;
                *(float4*)&xs[buf ^ 1][row][c4*4] = rx[q];
            }
#pragma unroll
            for (int q = 0; q < 2; ++q) {
                int idx = tid + q*256, row = idx >> 4, c4 = idx & 15;
                *(float4*)&ws[buf ^ 1][row][c4*4] = rw[q];
            }
            __syncthreads();
            buf ^= 1;
        }
    }

    float bv[4];
#pragma unroll
    for (int j = 0; j < 4; ++j) bv[j] = __ldg(bias + ob*64 + oq*4 + j);
#pragma unroll
    for (int i = 0; i < 8; ++i) {
        int slot = sblk*RS_PX + pq*8 + i;
        float4 o;
        o.x = fmaxf(__fadd_rn(acc[i][0], bv[0]), 0.f);
        o.y = fmaxf(__fadd_rn(acc[i][1], bv[1]), 0.f);
        o.z = fmaxf(__fadd_rn(acc[i][2], bv[2]), 0.f);
        o.w = fmaxf(__fadd_rn(acc[i][3], bv[3]), 0.f);
        *(float4*)(g_hex + ((size_t)n*CAND_MAX + slot)*512 + ob*64 + oq*4) = o;
    }
}

// ================= K7: exact per-anchor score/loc/key/box (R3 conv1x1 order) =================
__global__ __launch_bounds__(256) void rescore_anchor_kernel(
    const float* __restrict__ sw, const float* __restrict__ sb,
    const float* __restrict__ lw, const float* __restrict__ lb)
{
    const int n = blockIdx.y;
    const int i = blockIdx.x * 256 + threadIdx.x;
    if (i >= NANC) return;
    if (g_key[(size_t)n*NANC + i] < g_tcand[n]) return;
    const int a = i % NA, p = i / NA;
    const int slot = g_pixslot[n*4096 + p];
    if (slot < 0) return;
    const float* h = g_hex + ((size_t)n*CAND_MAX + slot)*512;
    const float* w0 = sw + (size_t)(2*a)*512;
    const float* w1 = sw + (size_t)(2*a + 1)*512;
    const float* wl0 = lw + (size_t)(4*a + 0)*512;
    const float* wl1 = lw + (size_t)(4*a + 1)*512;
    const float* wl2 = lw + (size_t)(4*a + 2)*512;
    const float* wl3 = lw + (size_t)(4*a + 3)*512;

    float s0 = 0.f, s1 = 0.f, l0 = 0.f, l1 = 0.f, l2 = 0.f, l3 = 0.f;
    for (int ic = 0; ic < 512; ic += 4) {
        float4 hv = *(const float4*)(h + ic);
        float ha[4] = {hv.x, hv.y, hv.z, hv.w};
#pragma unroll
        for (int q = 0; q < 4; ++q) {
            float hq = ha[q];
            s0 = __fmaf_rn(__ldg(w0 + ic + q), hq, s0);
            s1 = __fmaf_rn(__ldg(w1 + ic + q), hq, s1);
            l0 = __fmaf_rn(__ldg(wl0 + ic + q), hq, l0);
            l1 = __fmaf_rn(__ldg(wl1 + ic + q), hq, l1);
            l2 = __fmaf_rn(__ldg(wl2 + ic + q), hq, l2);
            l3 = __fmaf_rn(__ldg(wl3 + ic + q), hq, l3);
        }
    }
    s0 = __fadd_rn(s0, __ldg(sb + 2*a));
    s1 = __fadd_rn(s1, __ldg(sb + 2*a + 1));
    l0 = __fadd_rn(l0, __ldg(lb + 4*a + 0));
    l1 = __fadd_rn(l1, __ldg(lb + 4*a + 1));
    l2 = __fadd_rn(l2, __ldg(lb + 4*a + 2));
    l3 = __fadd_rn(l3, __ldg(lb + 4*a + 3));

    const int xx = p % WW, yy = p / WW;
    const double ratios[3] = {0.5, 1.0, 2.0};
    const double scales[3] = {8.0, 16.0, 32.0};
    double hh = (16.0 * scales[a % 3]) * sqrt(ratios[a / 3]);
    double wd = (16.0 * scales[a % 3]) * sqrt(1.0 / ratios[a / 3]);
    float a0 = (float)(8.0 - hh / 2.0) + (float)(yy * 16);
    float a1 = (float)(8.0 - wd / 2.0) + (float)(xx * 16);
    float a2 = (float)(8.0 + hh / 2.0) + (float)(yy * 16);
    float a3 = (float)(8.0 + wd / 2.0) + (float)(xx * 16);

    float haa = __fadd_rn(a2, -a0);
    float waa = __fadd_rn(a3, -a1);
    float cy = __fadd_rn(a0, __fmul_rn(0.5f, haa));
    float cx = __fadd_rn(a1, __fmul_rn(0.5f, waa));
    float cy2 = __fadd_rn(__fmul_rn(l0, haa), cy);
    float cx2 = __fadd_rn(__fmul_rn(l1, waa), cx);
    float h2 = __fmul_rn(expf(l2), haa);
    float w2 = __fmul_rn(expf(l3), waa);
    float b0 = __fadd_rn(cy2, -__fmul_rn(0.5f, h2));
    float b1 = __fadd_rn(cx2, -__fmul_rn(0.5f, w2));
    float b2 = __fadd_rn(cy2,  __fmul_rn(0.5f, h2));
    float b3 = __fadd_rn(cx2,  __fmul_rn(0.5f, w2));
    b0 = fminf(fmaxf(b0, 0.f), 1024.f);
    b1 = fminf(fmaxf(b1, 0.f), 1024.f);
    b2 = fminf(fmaxf(b2, 0.f), 1024.f);
    b3 = fminf(fmaxf(b3, 0.f), 1024.f);
    bool valid = ((b2 - b0) >= 16.f) && ((b3 - b1) >= 16.f);

    float m = fmaxf(s0, s1);
    float e0 = expf(s0 - m), e1 = expf(s1 - m);
    float fg = e1 / (e0 + e1);
    if (!valid) fg = -INFINITY;

    float* bp = g_boxes + ((size_t)n*NANC + i)*4;
    bp[0] = b0; bp[1] = b1; bp[2] = b2; bp[3] = b3;

    unsigned int kb = __float_as_uint(fg);
    unsigned int k  = (kb & 0x80000000u) ? ~kb : (kb | 0x80000000u);
    g_key[(size_t)n*NANC + i] =
        ((unsigned long long)k << 16) | (unsigned long long)(65535 - i);
}

// ================= K8: exact top-2000 =================
__global__ __launch_bounds__(1024) void topk_kernel()
{
    const int n = blockIdx.x;
    const int tid = threadIdx.x;
    __shared__ unsigned int hist[256];
    __shared__ unsigned long long ssort[2048];
    __shared__ unsigned long long s_prefix;
    __shared__ int s_rank;
    __shared__ int s_cnt;

    const unsigned long long* key = g_key + (size_t)n * NANC;
    if (tid == 0) { s_prefix = 0ULL; s_rank = PRE_NMS - 1; s_cnt = 0; }
    if (tid < 32) g_keep0[n*32 + tid] = 0ULL;
    __syncthreads();

    for (int d = 5; d >= 0; --d) {
        if (tid < 256) hist[tid] = 0u;
        __syncthreads();
        unsigned long long pref = s_prefix;
        int sh = (d + 1) * 8;
        for (int idx = tid; idx < NANC; idx += 1024) {
            unsigned long long k = key[idx];
            if ((k >> sh) == (pref >> sh))
                atomicAdd(&hist[(unsigned)(k >> (8*d)) & 255u], 1u);
        }
        __syncthreads();
        if (tid == 0) {
            int cum = 0, rank = s_rank;
            for (int v = 255; v >= 0; --v) {
                int c = (int)hist[v];
                if (cum + c > rank) {
                    s_prefix = pref | ((unsigned long long)(unsigned)v << (8*d));
                    s_rank = rank - cum;
                    break;
                }
                cum += c;
            }
        }
        __syncthreads();
    }
    unsigned long long T = s_prefix;
    __syncthreads();
    for (int idx = tid; idx < NANC; idx += 1024) {
        unsigned long long k = key[idx];
        if (k >= T) {
            int pos = atomicAdd(&s_cnt, 1);
            if (pos < 2048) ssort[pos] = k;
        }
    }
    __syncthreads();
    int cnt = s_cnt;
    for (int idx = cnt + tid; idx < 2048; idx += 1024) ssort[idx] = 0ULL;
    __syncthreads();

    for (int ksz = 2; ksz <= 2048; ksz <<= 1) {
        for (int j = ksz >> 1; j > 0; j >>= 1) {
            for (int idx = tid; idx < 2048; idx += 1024) {
                int ixj = idx ^ j;
                if (ixj > idx) {
                    unsigned long long va = ssort[idx], vb = ssort[ixj];
                    bool desc = ((idx & ksz) == 0);
                    if (desc ? (va < vb) : (va > vb)) { ssort[idx] = vb; ssort[ixj] = va; }
                }
            }
            __syncthreads();
        }
    }

    for (int r = tid; r < PRE_NMS; r += 1024) {
        unsigned long long comp = ssort[r];
        int idx = 65535 - (int)(comp & 0xFFFFULL);
        const float4 bv = *reinterpret_cast<const float4*>(g_boxes + ((size_t)n*NANC + idx)*4);
        *reinterpret_cast<float4*>(g_selbox + ((size_t)n*PRE_NMS + r)*4) = bv;
        unsigned int fk = (unsigned)(comp >> 16);
        if (fk > 0x007FFFFFu)
            atomicOr(&g_keep0[n*32 + (r >> 6)], 1ULL << (r & 63));
    }
}

// ================= K9: NMS mask =================
__global__ __launch_bounds__(512) void nms_mask_kernel()
{
    const int n = blockIdx.y;
    const int i = blockIdx.x * 16 + threadIdx.y;
    const int t = threadIdx.x;
    __shared__ float4 bj[PRE_NMS];
    int ftid = threadIdx.y * 32 + threadIdx.x;
    for (int idx = ftid; idx < PRE_NMS; idx += 512)
        bj[idx] = *reinterpret_cast<const float4*>(g_selbox + ((size_t)n*PRE_NMS + idx)*4);
    __syncthreads();

    float4 bi = bj[i];
    float ai = (bi.z - bi.x) * (bi.w - bi.y);
    unsigned long long bits = 0ULL;
    int jbase = t << 6;
#pragma unroll 4
    for (int jj = 0; jj < 64; ++jj) {
        int j = jbase + jj;
        if (j >= PRE_NMS) break;
        if (j <= i) continue;
        float4 b = bj[j];
        float aj = (b.z - b.x) * (b.w - b.y);
        float ty = fmaxf(bi.x, b.x), tx = fmaxf(bi.y, b.y);
        float by = fminf(bi.z, b.z), bx = fminf(bi.w, b.w);
        float ih = fmaxf(by - ty, 0.f), iw = fmaxf(bx - tx, 0.f);
        float inter = ih * iw;
        float iou = inter / (ai + aj - inter + 1e-9f);
        if (iou > 0.7f) bits |= (1ULL << jj);
    }
    g_mask[((size_t)n*PRE_NMS + i)*32 + t] = bits;
}

// ================= K10: greedy scan =================
__global__ __launch_bounds__(32) void scan_kernel(float* __restrict__ out)
{
    const int n = blockIdx.x;
    const int t = threadIdx.x;
    __shared__ unsigned long long rem[32];
    __shared__ unsigned long long kw[32];
    __shared__ int s_flag;
    rem[t] = 0ULL;
    kw[t] = g_keep0[n*32 + t];
    __syncthreads();

    int cnt = 0;
    for (int r = 0; r < PRE_NMS; ++r) {
        if (t == 0) {
            unsigned long long bit = 1ULL << (r & 63);
            s_flag = ((kw[r >> 6] & bit) != 0ULL && (rem[r >> 6] & bit) == 0ULL) ? 1 : 0;
        }
        __syncthreads();
        int f = s_flag;
        __syncthreads();
        if (f) {
            rem[t] |= g_mask[((size_t)n*PRE_NMS + r)*32 + t];
            if (t < 4)
                out[OFF_ROIS + ((size_t)n*POST_NMS + cnt)*4 + t] =
                    g_selbox[((size_t)n*PRE_NMS + r)*4 + t];
            cnt++;
        }
        __syncthreads();
        if (f && cnt == POST_NMS) break;
    }
    for (int idx = cnt*4 + t; idx < POST_NMS*4; idx += 32)
        out[OFF_ROIS + (size_t)n*POST_NMS*4 + idx] = 0.f;
    for (int idx = t; idx < POST_NMS; idx += 32)
        out[OFF_IND + (size_t)n*POST_NMS + idx] = (float)n;
}

// ================= launch =================
extern "C" void kernel_launch(void* const* d_in, const int* in_sizes, int n_in,
                              void* d_out, int out_size)
{
    const float* x  = (const float*)d_in[0];
    const float* w1 = (const float*)d_in[1];
    const float* b1 = (const float*)d_in[2];
    const float* sw = (const float*)d_in[3];
    const float* sb = (const float*)d_in[4];
    const float* lw = (const float*)d_in[5];
    const float* lb = (const float*)d_in[6];
    float* out = (float*)d_out;

    cudaFuncSetAttribute(conv3x3_mma_kernel,
                         cudaFuncAttributeMaxDynamicSharedMemorySize, SMEM_MMA_TOTAL);

    split_w_kernel<<<512, 512>>>(w1);
    prep_wg_kernel<<<KTOT, 256>>>(w1);
    split_x_kernel<<<dim3(8, 64, NB), 256>>>(x);
    conv3x3_mma_kernel<<<dim3(32, 8, NB), 256, SMEM_MMA_TOTAL>>>(b1);
    conv1x1_kernel<<<dim3(64, NB), 256>>>(sw, sb, lw, lb);
    boxes_kernel<<<dim3((NANC + 255) / 256, NB), 256>>>(out);
    cand_kernel<<<NB, 1024>>>();
    gather_kernel<<<dim3(KTOT, NB), 256>>>(x);
    rescore_gemm_kernel<<<dim3(CAND_MAX/RS_PX, 8, NB), 256>>>(b1);
    rescore_anchor_kernel<<<dim3((NANC + 255) / 256, NB), 256>>>(sw, sb, lw, lb);
    topk_kernel<<<NB, 1024>>>();
    nms_mask_kernel<<<dim3(PRE_NMS / 16, NB), dim3(32, 16)>>>();
    scan_kernel<<<NB, 32>>>(out);
}

// round 15
// speedup vs baseline: 1.0360x; 1.0360x over previous
#include <cuda_runtime.h>
#include <cuda_bf16.h>
#include <math.h>
#include <stdint.h>

// ---------------- problem constants ----------------
#define NB      8
#define CIN     512
#define HH      64
#define WW      64
#define OC      512
#define NA      9
#define NANC    (HH*WW*NA)  // 36864
#define PRE_NMS 2000
#define POST_NMS 300
#define CAND_MAX 2048
#define CAND_RANK 2047
#define KTOT 4608           // 9 taps x 512 ic, R3 k-order
#define RS_PX 128           // rescore GEMM pixel tile

#define OFF_LOCS   0
#define OFF_SCORES (NB*NANC*4)
#define OFF_ROIS   (OFF_SCORES + NB*NANC*2)
#define OFF_IND    (OFF_ROIS + NB*POST_NMS*4)
#define OFF_ANC    (OFF_IND + NB*POST_NMS)

// ---------------- scratch ----------------
__device__ float g_h[NB*OC*HH*WW];
__device__ float g_score[NB*18*HH*WW];
__device__ float g_loc[NB*36*HH*WW];
__device__ float g_boxes[NB*NANC*4];
__device__ unsigned long long g_key[NB*NANC];
__device__ float g_selbox[NB*PRE_NMS*4];
__device__ unsigned long long g_keep0[NB*32];
__device__ unsigned long long g_mask[(size_t)NB*PRE_NMS*32];

// bf16 2-way splits (approx conv): x channel-last [s][n][y][x][ic], w [s][tap][oc][ic]
__device__ __align__(16) __nv_bfloat16 g_xs[(size_t)2*NB*64*64*512];
__device__ __align__(16) __nv_bfloat16 g_ws[(size_t)2*9*512*512];

// exact-rescore scratch
__device__ __align__(16) float g_wg[(size_t)KTOT*512];                 // [k][oc]
__device__ __align__(16) float g_gather[(size_t)NB*KTOT*CAND_MAX];    // [n][k][slot]
__device__ __align__(16) float g_hex[(size_t)NB*CAND_MAX*512];        // [n][slot][oc]
__device__ unsigned long long g_tcand[NB];
__device__ int g_npx[NB];
__device__ unsigned short g_plist[NB*4096];
__device__ short g_pixslot[NB*4096];

// ---------------- helpers ----------------
__device__ __forceinline__ uint32_t smem_u32(const void* p) {
    uint32_t a;
    asm("{ .reg .u64 t; cvta.to.shared.u64 t, %1; cvt.u32.u64 %0, t; }" : "=r"(a) : "l"(p));
    return a;
}
#define SWZ(o) ((o) ^ (((o) >> 3) & 0x70))

__device__ __forceinline__ void cp16(uint32_t dst, const void* src, int nbytes) {
    asm volatile("cp.async.cg.shared.global [%0], [%1], 16, %2;"
                 :: "r"(dst), "l"(src), "r"(nbytes) : "memory");
}
#define CP_COMMIT() asm volatile("cp.async.commit_group;" ::: "memory")

__device__ __forceinline__ void ldx4(uint32_t* r, uint32_t addr) {
    asm volatile("ldmatrix.sync.aligned.m8n8.x4.shared.b16 {%0,%1,%2,%3}, [%4];"
                 : "=r"(r[0]), "=r"(r[1]), "=r"(r[2]), "=r"(r[3]) : "r"(addr));
}
__device__ __forceinline__ void mma16816(float* d, const uint32_t* a, uint32_t b0, uint32_t b1) {
    asm volatile("mma.sync.aligned.m16n8k16.row.col.f32.bf16.bf16.f32 "
                 "{%0,%1,%2,%3}, {%4,%5,%6,%7}, {%8,%9}, {%0,%1,%2,%3};"
                 : "+f"(d[0]), "+f"(d[1]), "+f"(d[2]), "+f"(d[3])
                 : "r"(a[0]), "r"(a[1]), "r"(a[2]), "r"(a[3]), "r"(b0), "r"(b1));
}

// ================= prep: split w -> 2x bf16 =================
__global__ __launch_bounds__(512) void split_w_kernel(const float* __restrict__ w)
{
    const int oc = blockIdx.x, ic = threadIdx.x;
    const float* src = w + ((size_t)oc*CIN + ic)*9;
    const size_t ss = (size_t)9*512*512;
#pragma unroll
    for (int t = 0; t < 9; ++t) {
        float v = src[t];
        __nv_bfloat16 b0 = __float2bfloat16_rn(v);
        float r1 = v - __bfloat162float(b0);
        __nv_bfloat16 b1 = __float2bfloat16_rn(r1);
        size_t o = ((size_t)t*512 + oc)*512 + ic;
        g_ws[o] = b0; g_ws[o + ss] = b1;
    }
}

// ================= prep: weights in R3 k-order [k][oc] =================
__global__ __launch_bounds__(256) void prep_wg_kernel(const float* __restrict__ w)
{
    const int k = blockIdx.x;
    const int cc = k / 72, r = k % 72, ici = r / 9, tap = r % 9;
    const int ky = tap / 3, kx = tap % 3, ch = cc*8 + ici;
    for (int oc = threadIdx.x; oc < 512; oc += 256)
        g_wg[(size_t)k*512 + oc] = w[(((size_t)oc*512 + ch)*3 + ky)*3 + kx];
}

// ================= prep: split x -> 2x bf16 channel-last =================
__global__ __launch_bounds__(256) void split_x_kernel(const float* __restrict__ x)
{
    __shared__ float tile[64][65];
    const int c0 = blockIdx.x * 64, y = blockIdx.y, n = blockIdx.z;
    const int t = threadIdx.x;
    {
        int ic = t >> 2, xq = (t & 3) * 16;
        const float4* src = (const float4*)(x + (((size_t)n*CIN + c0 + ic)*64 + y)*64 + xq);
#pragma unroll
        for (int k = 0; k < 4; ++k) {
            float4 v = src[k];
            tile[ic][xq + 4*k + 0] = v.x; tile[ic][xq + 4*k + 1] = v.y;
            tile[ic][xq + 4*k + 2] = v.z; tile[ic][xq + 4*k + 3] = v.w;
        }
    }
    __syncthreads();
    const int xw = t >> 2, ic0 = (t & 3) * 16;
    __align__(16) __nv_bfloat16 o0[16], o1[16];
#pragma unroll
    for (int k = 0; k < 16; ++k) {
        float v = tile[ic0 + k][xw];
        o0[k] = __float2bfloat16_rn(v);
        float r1 = v - __bfloat162float(o0[k]);
        o1[k] = __float2bfloat16_rn(r1);
    }
    const size_t ss = (size_t)NB*64*64*512;
    size_t base = (((size_t)n*64 + y)*64 + xw)*512 + c0 + ic0;
    ((uint4*)(g_xs + base))[0]        = ((uint4*)o0)[0];
    ((uint4*)(g_xs + base))[1]        = ((uint4*)o0)[1];
    ((uint4*)(g_xs + base + ss))[0]   = ((uint4*)o1)[0];
    ((uint4*)(g_xs + base + ss))[1]   = ((uint4*)o1)[1];
}

// ================= K1: approx 3x3 conv via mma.sync bf16 (2-split, 3-product) =================
// CTA: 128 pixels x 64 oc. 8 warps (4 M x 2 N), warp tile 32x32.
// SMEM: 2 buf x 2 splits x (A 16KB + B 8KB) = 96 KB -> 2 CTAs/SM.
#define SMEM_MMA_TOTAL (2*2*16384 + 2*2*8192)

__global__ void __launch_bounds__(256, 2) conv3x3_mma_kernel(const float* __restrict__ bias)
{
    extern __shared__ char smem[];
    const uint32_t sb = smem_u32(smem);
    const int n = blockIdx.z, ntile = blockIdx.y, mtile = blockIdx.x;
    const int y0 = mtile * 2;
    const int tid = threadIdx.x, wid = tid >> 5, lane = tid & 31;
    const int wm = wid & 3, wn = wid >> 2;
    const uint32_t A0 = sb, B0 = sb + 4*16384;

    const int r = tid >> 1, hq = tid & 1;      // A loader: pixel row, 64B half
    const int rb = tid >> 2, qb = tid & 3;     // B loader: oc row, 32B quarter
    const size_t xs_ss = (size_t)NB*64*64*512;
    const size_t ws_ss = (size_t)9*512*512;

    float acc[2][2][8];
#pragma unroll
    for (int a = 0; a < 2; ++a)
#pragma unroll
        for (int b = 0; b < 2; ++b)
#pragma unroll
            for (int c = 0; c < 8; ++c) acc[a][b][c] = 0.f;

    auto issue = [&](int chunk, int buf) {
        const int tap = chunk >> 3, c0 = (chunk & 7) << 6;
        const int ky = tap / 3, kx = tap % 3;
        const int yi = y0 + (r >> 6) + ky - 1;
        const int xi = (r & 63) + kx - 1;
        const bool ok = ((unsigned)yi < 64u) && ((unsigned)xi < 64u);
        const int asz = ok ? 16 : 0;
        const size_t aoff = (((size_t)n*64 + (ok ? yi : 0))*64 + (ok ? xi : 0))*512 + c0 + hq*32;
        const uint32_t bo = (uint32_t)r*128 + (uint32_t)hq*64;
        const size_t boff = ((size_t)tap*512 + (size_t)(ntile*64 + rb))*512 + c0 + qb*16;
        const uint32_t bb = (uint32_t)rb*128 + (uint32_t)qb*32;
#pragma unroll
        for (int s = 0; s < 2; ++s) {
            const char* srcA = (const char*)(g_xs + s*xs_ss + aoff);
            uint32_t dA = A0 + (buf*2 + s)*16384;
            cp16(dA + SWZ(bo +  0), srcA +  0, asz);
            cp16(dA + SWZ(bo + 16), srcA + 16, asz);
            cp16(dA + SWZ(bo + 32), srcA + 32, asz);
            cp16(dA + SWZ(bo + 48), srcA + 48, asz);
            const char* srcB = (const char*)(g_ws + s*ws_ss + boff);
            uint32_t dB = B0 + (buf*2 + s)*8192;
            cp16(dB + SWZ(bb +  0), srcB +  0, 16);
            cp16(dB + SWZ(bb + 16), srcB + 16, 16);
        }
        CP_COMMIT();
    };

    const int g8 = lane >> 3, r8 = lane & 7;
    const int a_row = wm*32 + (g8 & 1)*8 + r8;      // + mt*16
    const int a_kb  = (g8 >> 1)*16;
    const int b_row = wn*32 + (g8 >> 1)*8 + r8;     // + nt*16
    const int b_kb  = (g8 & 1)*16;

    // 3 products: a0b0, a1b0, a0b1 (a1b1 dropped: ~2^-18 relative)
    const int SA[3] = {0, 1, 0};
    const int SB[3] = {0, 0, 1};

    issue(0, 0);

    for (int c = 0; c < 72; ++c) {
        const int buf = c & 1;
        if (c + 1 < 72) {
            issue(c + 1, buf ^ 1);
            asm volatile("cp.async.wait_group 1;" ::: "memory");
        } else {
            asm volatile("cp.async.wait_group 0;" ::: "memory");
        }
        __syncthreads();

        const uint32_t Ab = A0 + buf*2*16384;
        const uint32_t Bb = B0 + buf*2*8192;
#pragma unroll
        for (int ks = 0; ks < 4; ++ks) {
            uint32_t afr[2][2][4];
#pragma unroll
            for (int s = 0; s < 2; ++s)
#pragma unroll
                for (int mt = 0; mt < 2; ++mt)
                    ldx4(afr[s][mt], Ab + s*16384 +
                         (uint32_t)SWZ((a_row + mt*16)*128 + ks*32 + a_kb));
#pragma unroll
            for (int nt = 0; nt < 2; ++nt) {
                uint32_t bfr[2][4];
#pragma unroll
                for (int s = 0; s < 2; ++s)
                    ldx4(bfr[s], Bb + s*8192 +
                         (uint32_t)SWZ((b_row + nt*16)*128 + ks*32 + b_kb));
#pragma unroll
                for (int p = 0; p < 3; ++p) {
                    const int s = SA[p], t = SB[p];
#pragma unroll
                    for (int mt = 0; mt < 2; ++mt) {
                        mma16816(&acc[mt][nt][0], afr[s][mt], bfr[t][0], bfr[t][1]);
                        mma16816(&acc[mt][nt][4], afr[s][mt], bfr[t][2], bfr[t][3]);
                    }
                }
            }
        }
        __syncthreads();
    }

    // epilogue: bias + relu -> g_h [n][oc][y][x]
#pragma unroll
    for (int mt = 0; mt < 2; ++mt) {
        const int pix0 = mtile*128 + wm*32 + mt*16 + (lane >> 2);
#pragma unroll
        for (int nt = 0; nt < 2; ++nt) {
#pragma unroll
            for (int h8 = 0; h8 < 2; ++h8) {
                const int oc = ntile*64 + wn*32 + nt*16 + h8*8 + (lane & 3)*2;
                const float b0 = __ldg(bias + oc), b1 = __ldg(bias + oc + 1);
#pragma unroll
                for (int rr = 0; rr < 2; ++rr) {
                    const int pix = pix0 + rr*8;
                    const int y = pix >> 6, xw = pix & 63;
                    float v0 = acc[mt][nt][h8*4 + rr*2 + 0] + b0;
                    float v1 = acc[mt][nt][h8*4 + rr*2 + 1] + b1;
                    g_h[(((size_t)n*OC + oc    )*64 + y)*64 + xw] = fmaxf(v0, 0.f);
                    g_h[(((size_t)n*OC + oc + 1)*64 + y)*64 + xw] = fmaxf(v1, 0.f);
                }
            }
        }
    }
}

// ================= K2: approx 1x1 convs =================
__global__ __launch_bounds__(256) void conv1x1_kernel(
    const float* __restrict__ sw, const float* __restrict__ sb,
    const float* __restrict__ lw, const float* __restrict__ lb)
{
    const int n = blockIdx.y;
    const int y = blockIdx.x;
    const int tid = threadIdx.x;
    const int xcol = tid & 63;
    const int cg = tid >> 6;

    __shared__ float hs[64][64];
    __shared__ float wsc[56][64];

    float acc[14];
#pragma unroll
    for (int j = 0; j < 14; ++j) acc[j] = 0.f;

    for (int c0 = 0; c0 < CIN; c0 += 64) {
        for (int idx = tid; idx < 64*64; idx += 256) {
            int ic = idx >> 6, xx = idx & 63;
            hs[ic][xx] = g_h[(((size_t)n*OC + c0 + ic)*HH + y)*WW + xx];
        }
        for (int idx = tid; idx < 56*64; idx += 256) {
            int c = idx >> 6, ic = idx & 63;
            float v = 0.f;
            if (c < 18) v = sw[(size_t)c*CIN + c0 + ic];
            else if (c < 54) v = lw[(size_t)(c-18)*CIN + c0 + ic];
            wsc[c][ic] = v;
        }
        __syncthreads();
#pragma unroll 8
        for (int ic = 0; ic < 64; ++ic) {
            float xv = hs[ic][xcol];
#pragma unroll
            for (int j = 0; j < 14; ++j)
                acc[j] = fmaf(wsc[cg + 4*j][ic], xv, acc[j]);
        }
        __syncthreads();
    }
    int p = y * WW + xcol;
#pragma unroll
    for (int j = 0; j < 14; ++j) {
        int c = cg + 4*j;
        if (c < 18)       g_score[((size_t)n*18 + c)*4096 + p] = acc[j] + sb[c];
        else if (c < 54)  g_loc[((size_t)n*36 + (c-18))*4096 + p] = acc[j] + lb[c-18];
    }
}

// ================= K3: approx boxes / keys + full outputs =================
__global__ __launch_bounds__(256) void boxes_kernel(float* __restrict__ out)
{
    const int n = blockIdx.y;
    const int i = blockIdx.x * 256 + threadIdx.x;
    if (i >= NANC) return;
    const int a  = i % NA;
    const int p  = i / NA;
    const int xx = p % WW;
    const int yy = p / WW;

    float s0 = g_score[((size_t)n*18 + 2*a    )*4096 + p];
    float s1 = g_score[((size_t)n*18 + 2*a + 1)*4096 + p];
    out[OFF_SCORES + ((size_t)n*NANC + i)*2 + 0] = s0;
    out[OFF_SCORES + ((size_t)n*NANC + i)*2 + 1] = s1;

    float l0 = g_loc[((size_t)n*36 + a*4 + 0)*4096 + p];
    float l1 = g_loc[((size_t)n*36 + a*4 + 1)*4096 + p];
    float l2 = g_loc[((size_t)n*36 + a*4 + 2)*4096 + p];
    float l3 = g_loc[((size_t)n*36 + a*4 + 3)*4096 + p];
    out[OFF_LOCS + ((size_t)n*NANC + i)*4 + 0] = l0;
    out[OFF_LOCS + ((size_t)n*NANC + i)*4 + 1] = l1;
    out[OFF_LOCS + ((size_t)n*NANC + i)*4 + 2] = l2;
    out[OFF_LOCS + ((size_t)n*NANC + i)*4 + 3] = l3;

    const double ratios[3] = {0.5, 1.0, 2.0};
    const double scales[3] = {8.0, 16.0, 32.0};
    double hh = (16.0 * scales[a % 3]) * sqrt(ratios[a / 3]);
    double wd = (16.0 * scales[a % 3]) * sqrt(1.0 / ratios[a / 3]);
    float ab0 = (float)(8.0 - hh / 2.0);
    float ab1 = (float)(8.0 - wd / 2.0);
    float ab2 = (float)(8.0 + hh / 2.0);
    float ab3 = (float)(8.0 + wd / 2.0);
    float a0 = ab0 + (float)(yy * 16);
    float a1 = ab1 + (float)(xx * 16);
    float a2 = ab2 + (float)(yy * 16);
    float a3 = ab3 + (float)(xx * 16);
    if (n == 0) {
        out[OFF_ANC + (size_t)i*4 + 0] = a0;
        out[OFF_ANC + (size_t)i*4 + 1] = a1;
        out[OFF_ANC + (size_t)i*4 + 2] = a2;
        out[OFF_ANC + (size_t)i*4 + 3] = a3;
    }

    float ha = __fadd_rn(a2, -a0);
    float wa = __fadd_rn(a3, -a1);
    float cy = __fadd_rn(a0, __fmul_rn(0.5f, ha));
    float cx = __fadd_rn(a1, __fmul_rn(0.5f, wa));
    float cy2 = __fadd_rn(__fmul_rn(l0, ha), cy);
    float cx2 = __fadd_rn(__fmul_rn(l1, wa), cx);
    float h2 = __fmul_rn(expf(l2), ha);
    float w2 = __fmul_rn(expf(l3), wa);
    float b0 = __fadd_rn(cy2, -__fmul_rn(0.5f, h2));
    float b1 = __fadd_rn(cx2, -__fmul_rn(0.5f, w2));
    float b2 = __fadd_rn(cy2,  __fmul_rn(0.5f, h2));
    float b3 = __fadd_rn(cx2,  __fmul_rn(0.5f, w2));
    b0 = fminf(fmaxf(b0, 0.f), 1024.f);
    b1 = fminf(fmaxf(b1, 0.f), 1024.f);
    b2 = fminf(fmaxf(b2, 0.f), 1024.f);
    b3 = fminf(fmaxf(b3, 0.f), 1024.f);
    bool valid = ((b2 - b0) >= 16.f) && ((b3 - b1) >= 16.f);

    float m = fmaxf(s0, s1);
    float e0 = expf(s0 - m), e1 = expf(s1 - m);
    float fg = e1 / (e0 + e1);
    if (!valid) fg = -INFINITY;

    float* bp = g_boxes + ((size_t)n*NANC + i)*4;
    bp[0] = b0; bp[1] = b1; bp[2] = b2; bp[3] = b3;

    unsigned int kb = __float_as_uint(fg);
    unsigned int k  = (kb & 0x80000000u) ? ~kb : (kb | 0x80000000u);
    g_key[(size_t)n*NANC + i] =
        ((unsigned long long)k << 16) | (unsigned long long)(65535 - i);
}

// ================= K4: candidate selection (threshold + pixel compaction) =================
__global__ __launch_bounds__(1024) void cand_kernel()
{
    const int n = blockIdx.x;
    const int tid = threadIdx.x;
    const int lane = tid & 31, wid = tid >> 5;
    __shared__ unsigned int hist[256];
    __shared__ unsigned long long s_prefix;
    __shared__ int s_rank;
    __shared__ unsigned char flag[4096];
    __shared__ int wsum[32];

    const unsigned long long* key = g_key + (size_t)n * NANC;
    if (tid == 0) { s_prefix = 0ULL; s_rank = CAND_RANK; }
    __syncthreads();

    for (int d = 5; d >= 0; --d) {
        if (tid < 256) hist[tid] = 0u;
        __syncthreads();
        unsigned long long pref = s_prefix;
        int sh = (d + 1) * 8;
        for (int idx = tid; idx < NANC; idx += 1024) {
            unsigned long long k = key[idx];
            if ((k >> sh) == (pref >> sh))
                atomicAdd(&hist[(unsigned)(k >> (8*d)) & 255u], 1u);
        }
        __syncthreads();
        if (tid == 0) {
            int cum = 0, rank = s_rank;
            for (int v = 255; v >= 0; --v) {
                int c = (int)hist[v];
                if (cum + c > rank) {
                    s_prefix = pref | ((unsigned long long)(unsigned)v << (8*d));
                    s_rank = rank - cum;
                    break;
                }
                cum += c;
            }
        }
        __syncthreads();
    }
    const unsigned long long T = s_prefix;
    if (tid == 0) g_tcand[n] = T;

    for (int p = tid; p < 4096; p += 1024) flag[p] = 0;
    __syncthreads();
    for (int i = tid; i < NANC; i += 1024)
        if (key[i] >= T) flag[i / 9] = 1;
    __syncthreads();

    int have[4], cnt = 0;
#pragma unroll
    for (int j = 0; j < 4; ++j) { have[j] = flag[tid*4 + j]; cnt += have[j]; }
    int incl = cnt;
#pragma unroll
    for (int off = 1; off < 32; off <<= 1) {
        int v = __shfl_up_sync(0xffffffffu, incl, off);
        if (lane >= off) incl += v;
    }
    if (lane == 31) wsum[wid] = incl;
    __syncthreads();
    if (wid == 0) {
        int v = wsum[lane];
        int inc2 = v;
#pragma unroll
        for (int off = 1; off < 32; off <<= 1) {
            int u = __shfl_up_sync(0xffffffffu, inc2, off);
            if (lane >= off) inc2 += u;
        }
        wsum[lane] = inc2 - v;   // exclusive
    }
    __syncthreads();
    int base = wsum[wid] + (incl - cnt);
    int run = 0;
#pragma unroll
    for (int j = 0; j < 4; ++j) {
        int p = tid*4 + j;
        if (have[j]) {
            int s = base + run; run++;
            g_plist[n*4096 + s] = (unsigned short)p;
            g_pixslot[n*4096 + p] = (short)s;
        } else {
            g_pixslot[n*4096 + p] = -1;
        }
    }
    if (tid == 1023) g_npx[n] = base + cnt;
}

// ================= K5: gather candidate im2col x in R3 k-order [n][k][slot] =================
__global__ __launch_bounds__(256) void gather_kernel(const float* __restrict__ x)
{
    const int n = blockIdx.y, k = blockIdx.x;
    const int cc = k / 72, r = k % 72, ici = r / 9, tap = r % 9;
    const int ky = tap / 3, kx = tap % 3, ch = cc*8 + ici;
    const int npx = g_npx[n];
    int lim = (npx + RS_PX - 1) & ~(RS_PX - 1);
    if (lim > CAND_MAX) lim = CAND_MAX;
    for (int s = threadIdx.x; s < lim; s += 256) {
        float v = 0.f;
        if (s < npx) {
            int pix = g_plist[n*4096 + s];
            int y = pix >> 6, xx = pix & 63;
            int yi = y + ky - 1, xi = xx + kx - 1;
            if ((unsigned)yi < 64u && (unsigned)xi < 64u)
                v = x[(((size_t)n*512 + ch)*64 + yi)*64 + xi];
        }
        g_gather[((size_t)n*KTOT + k)*CAND_MAX + s] = v;
    }
}

// ================= K6: exact rescore GEMM — bit-exact R3 fmaf chains =================
// CTA: 128 px x 64 oc, 256 threads, 8x4 acc/thread. Sequential k 0..4607 per output.
// SMEM: 2 buf x (xs 16KB + ws 8KB) = 48KB. __launch_bounds__(256,2): 128-reg budget,
// no spills (R14's (256,3) capped regs at ~84 and spilled the prefetch registers).
__global__ void __launch_bounds__(256, 2) rescore_gemm_kernel(const float* __restrict__ bias)
{
    __shared__ float xs[2][32][128];
    __shared__ float ws[2][32][64];
    const int sblk = blockIdx.x, ob = blockIdx.y, n = blockIdx.z;
    if (sblk * RS_PX >= g_npx[n]) return;
    const int tid = threadIdx.x;
    const int pq = tid & 15, oq = tid >> 4;      // 16 px-groups of 8, 16 oc-groups of 4
    const size_t gbase = (size_t)n*KTOT*CAND_MAX + (size_t)sblk*RS_PX;

    float acc[8][4];
#pragma unroll
    for (int i = 0; i < 8; ++i)
#pragma unroll
        for (int j = 0; j < 4; ++j) acc[i][j] = 0.f;

    // preload kt=0
#pragma unroll
    for (int q = 0; q < 4; ++q) {
        int idx = tid + q*256, row = idx >> 5, c4 = idx & 31;
        *(float4*)&xs[0][row][c4*4] =
            *(const float4*)(g_gather + gbase + (size_t)row*CAND_MAX + c4*4);
    }
#pragma unroll
    for (int q = 0; q < 2; ++q) {
        int idx = tid + q*256, row = idx >> 4, c4 = idx & 15;
        *(float4*)&ws[0][row][c4*4] =
            *(const float4*)(g_wg + (size_t)row*512 + ob*64 + c4*4);
    }
    __syncthreads();
    int buf = 0;

    for (int kt = 0; kt < 144; ++kt) {
        float4 rx[4], rw[2];
        if (kt < 143) {
            const int k1 = (kt + 1) * 32;
#pragma unroll
            for (int q = 0; q < 4; ++q) {
                int idx = tid + q*256, row = idx >> 5, c4 = idx & 31;
                rx[q] = *(const float4*)(g_gather + gbase + (size_t)(k1 + row)*CAND_MAX + c4*4);
            }
#pragma unroll
            for (int q = 0; q < 2; ++q) {
                int idx = tid + q*256, row = idx >> 4, c4 = idx & 15;
                rw[q] = *(const float4*)(g_wg + (size_t)(k1 + row)*512 + ob*64 + c4*4);
            }
        }
#pragma unroll
        for (int kk = 0; kk < 32; ++kk) {
            float4 xv0 = *(float4*)&xs[buf][kk][pq*8];
            float4 xv1 = *(float4*)&xs[buf][kk][pq*8 + 4];
            float4 wv  = *(float4*)&ws[buf][kk][oq*4];
            float xa[8] = {xv0.x, xv0.y, xv0.z, xv0.w, xv1.x, xv1.y, xv1.z, xv1.w};
            float wa[4] = {wv.x, wv.y, wv.z, wv.w};
#pragma unroll
            for (int i = 0; i < 8; ++i)
#pragma unroll
                for (int j = 0; j < 4; ++j)
                    acc[i][j] = __fmaf_rn(wa[j], xa[i], acc[i][j]);
        }
        if (kt < 143) {
            __syncthreads();
#pragma unroll
            for (int q = 0; q < 4; ++q) {
                int idx = tid + q*256, row = idx >> 5, c4 = idx & 31;
                *(float4*)&xs[buf ^ 1][row][c4*4] = rx[q];
            }
#pragma unroll
            for (int q = 0; q < 2; ++q) {
                int idx = tid + q*256, row = idx >> 4, c4 = idx & 15;
                *(float4*)&ws[buf ^ 1][row][c4*4] = rw[q];
            }
            __syncthreads();
            buf ^= 1;
        }
    }

    float bv[4];
#pragma unroll
    for (int j = 0; j < 4; ++j) bv[j] = __ldg(bias + ob*64 + oq*4 + j);
#pragma unroll
    for (int i = 0; i < 8; ++i) {
        int slot = sblk*RS_PX + pq*8 + i;
        float4 o;
        o.x = fmaxf(__fadd_rn(acc[i][0], bv[0]), 0.f);
        o.y = fmaxf(__fadd_rn(acc[i][1], bv[1]), 0.f);
        o.z = fmaxf(__fadd_rn(acc[i][2], bv[2]), 0.f);
        o.w = fmaxf(__fadd_rn(acc[i][3], bv[3]), 0.f);
        *(float4*)(g_hex + ((size_t)n*CAND_MAX + slot)*512 + ob*64 + oq*4) = o;
    }
}

// ================= K7: exact per-anchor score/loc/key/box (R3 conv1x1 order) =================
__global__ __launch_bounds__(256) void rescore_anchor_kernel(
    const float* __restrict__ sw, const float* __restrict__ sb,
    const float* __restrict__ lw, const float* __restrict__ lb)
{
    const int n = blockIdx.y;
    const int i = blockIdx.x * 256 + threadIdx.x;
    if (i >= NANC) return;
    if (g_key[(size_t)n*NANC + i] < g_tcand[n]) return;
    const int a = i % NA, p = i / NA;
    const int slot = g_pixslot[n*4096 + p];
    if (slot < 0) return;
    const float* h = g_hex + ((size_t)n*CAND_MAX + slot)*512;
    const float* w0 = sw + (size_t)(2*a)*512;
    const float* w1 = sw + (size_t)(2*a + 1)*512;
    const float* wl0 = lw + (size_t)(4*a + 0)*512;
    const float* wl1 = lw + (size_t)(4*a + 1)*512;
    const float* wl2 = lw + (size_t)(4*a + 2)*512;
    const float* wl3 = lw + (size_t)(4*a + 3)*512;

    float s0 = 0.f, s1 = 0.f, l0 = 0.f, l1 = 0.f, l2 = 0.f, l3 = 0.f;
    for (int ic = 0; ic < 512; ic += 4) {
        float4 hv = *(const float4*)(h + ic);
        float ha[4] = {hv.x, hv.y, hv.z, hv.w};
#pragma unroll
        for (int q = 0; q < 4; ++q) {
            float hq = ha[q];
            s0 = __fmaf_rn(__ldg(w0 + ic + q), hq, s0);
            s1 = __fmaf_rn(__ldg(w1 + ic + q), hq, s1);
            l0 = __fmaf_rn(__ldg(wl0 + ic + q), hq, l0);
            l1 = __fmaf_rn(__ldg(wl1 + ic + q), hq, l1);
            l2 = __fmaf_rn(__ldg(wl2 + ic + q), hq, l2);
            l3 = __fmaf_rn(__ldg(wl3 + ic + q), hq, l3);
        }
    }
    s0 = __fadd_rn(s0, __ldg(sb + 2*a));
    s1 = __fadd_rn(s1, __ldg(sb + 2*a + 1));
    l0 = __fadd_rn(l0, __ldg(lb + 4*a + 0));
    l1 = __fadd_rn(l1, __ldg(lb + 4*a + 1));
    l2 = __fadd_rn(l2, __ldg(lb + 4*a + 2));
    l3 = __fadd_rn(l3, __ldg(lb + 4*a + 3));

    const int xx = p % WW, yy = p / WW;
    const double ratios[3] = {0.5, 1.0, 2.0};
    const double scales[3] = {8.0, 16.0, 32.0};
    double hh = (16.0 * scales[a % 3]) * sqrt(ratios[a / 3]);
    double wd = (16.0 * scales[a % 3]) * sqrt(1.0 / ratios[a / 3]);
    float a0 = (float)(8.0 - hh / 2.0) + (float)(yy * 16);
    float a1 = (float)(8.0 - wd / 2.0) + (float)(xx * 16);
    float a2 = (float)(8.0 + hh / 2.0) + (float)(yy * 16);
    float a3 = (float)(8.0 + wd / 2.0) + (float)(xx * 16);

    float haa = __fadd_rn(a2, -a0);
    float waa = __fadd_rn(a3, -a1);
    float cy = __fadd_rn(a0, __fmul_rn(0.5f, haa));
    float cx = __fadd_rn(a1, __fmul_rn(0.5f, waa));
    float cy2 = __fadd_rn(__fmul_rn(l0, haa), cy);
    float cx2 = __fadd_rn(__fmul_rn(l1, waa), cx);
    float h2 = __fmul_rn(expf(l2), haa);
    float w2 = __fmul_rn(expf(l3), waa);
    float b0 = __fadd_rn(cy2, -__fmul_rn(0.5f, h2));
    float b1 = __fadd_rn(cx2, -__fmul_rn(0.5f, w2));
    float b2 = __fadd_rn(cy2,  __fmul_rn(0.5f, h2));
    float b3 = __fadd_rn(cx2,  __fmul_rn(0.5f, w2));
    b0 = fminf(fmaxf(b0, 0.f), 1024.f);
    b1 = fminf(fmaxf(b1, 0.f), 1024.f);
    b2 = fminf(fmaxf(b2, 0.f), 1024.f);
    b3 = fminf(fmaxf(b3, 0.f), 1024.f);
    bool valid = ((b2 - b0) >= 16.f) && ((b3 - b1) >= 16.f);

    float m = fmaxf(s0, s1);
    float e0 = expf(s0 - m), e1 = expf(s1 - m);
    float fg = e1 / (e0 + e1);
    if (!valid) fg = -INFINITY;

    float* bp = g_boxes + ((size_t)n*NANC + i)*4;
    bp[0] = b0; bp[1] = b1; bp[2] = b2; bp[3] = b3;

    unsigned int kb = __float_as_uint(fg);
    unsigned int k  = (kb & 0x80000000u) ? ~kb : (kb | 0x80000000u);
    g_key[(size_t)n*NANC + i] =
        ((unsigned long long)k << 16) | (unsigned long long)(65535 - i);
}

// ================= K8: exact top-2000 =================
__global__ __launch_bounds__(1024) void topk_kernel()
{
    const int n = blockIdx.x;
    const int tid = threadIdx.x;
    __shared__ unsigned int hist[256];
    __shared__ unsigned long long ssort[2048];
    __shared__ unsigned long long s_prefix;
    __shared__ int s_rank;
    __shared__ int s_cnt;

    const unsigned long long* key = g_key + (size_t)n * NANC;
    if (tid == 0) { s_prefix = 0ULL; s_rank = PRE_NMS - 1; s_cnt = 0; }
    if (tid < 32) g_keep0[n*32 + tid] = 0ULL;
    __syncthreads();

    for (int d = 5; d >= 0; --d) {
        if (tid < 256) hist[tid] = 0u;
        __syncthreads();
        unsigned long long pref = s_prefix;
        int sh = (d + 1) * 8;
        for (int idx = tid; idx < NANC; idx += 1024) {
            unsigned long long k = key[idx];
            if ((k >> sh) == (pref >> sh))
                atomicAdd(&hist[(unsigned)(k >> (8*d)) & 255u], 1u);
        }
        __syncthreads();
        if (tid == 0) {
            int cum = 0, rank = s_rank;
            for (int v = 255; v >= 0; --v) {
                int c = (int)hist[v];
                if (cum + c > rank) {
                    s_prefix = pref | ((unsigned long long)(unsigned)v << (8*d));
                    s_rank = rank - cum;
                    break;
                }
                cum += c;
            }
        }
        __syncthreads();
    }
    unsigned long long T = s_prefix;
    __syncthreads();
    for (int idx = tid; idx < NANC; idx += 1024) {
        unsigned long long k = key[idx];
        if (k >= T) {
            int pos = atomicAdd(&s_cnt, 1);
            if (pos < 2048) ssort[pos] = k;
        }
    }
    __syncthreads();
    int cnt = s_cnt;
    for (int idx = cnt + tid; idx < 2048; idx += 1024) ssort[idx] = 0ULL;
    __syncthreads();

    for (int ksz = 2; ksz <= 2048; ksz <<= 1) {
        for (int j = ksz >> 1; j > 0; j >>= 1) {
            for (int idx = tid; idx < 2048; idx += 1024) {
                int ixj = idx ^ j;
                if (ixj > idx) {
                    unsigned long long va = ssort[idx], vb = ssort[ixj];
                    bool desc = ((idx & ksz) == 0);
                    if (desc ? (va < vb) : (va > vb)) { ssort[idx] = vb; ssort[ixj] = va; }
                }
            }
            __syncthreads();
        }
    }

    for (int r = tid; r < PRE_NMS; r += 1024) {
        unsigned long long comp = ssort[r];
        int idx = 65535 - (int)(comp & 0xFFFFULL);
        const float4 bv = *reinterpret_cast<const float4*>(g_boxes + ((size_t)n*NANC + idx)*4);
        *reinterpret_cast<float4*>(g_selbox + ((size_t)n*PRE_NMS + r)*4) = bv;
        unsigned int fk = (unsigned)(comp >> 16);
        if (fk > 0x007FFFFFu)
            atomicOr(&g_keep0[n*32 + (r >> 6)], 1ULL << (r & 63));
    }
}

// ================= K9: NMS mask =================
__global__ __launch_bounds__(512) void nms_mask_kernel()
{
    const int n = blockIdx.y;
    const int i = blockIdx.x * 16 + threadIdx.y;
    const int t = threadIdx.x;
    __shared__ float4 bj[PRE_NMS];
    int ftid = threadIdx.y * 32 + threadIdx.x;
    for (int idx = ftid; idx < PRE_NMS; idx += 512)
        bj[idx] = *reinterpret_cast<const float4*>(g_selbox + ((size_t)n*PRE_NMS + idx)*4);
    __syncthreads();

    float4 bi = bj[i];
    float ai = (bi.z - bi.x) * (bi.w - bi.y);
    unsigned long long bits = 0ULL;
    int jbase = t << 6;
#pragma unroll 4
    for (int jj = 0; jj < 64; ++jj) {
        int j = jbase + jj;
        if (j >= PRE_NMS) break;
        if (j <= i) continue;
        float4 b = bj[j];
        float aj = (b.z - b.x) * (b.w - b.y);
        float ty = fmaxf(bi.x, b.x), tx = fmaxf(bi.y, b.y);
        float by = fminf(bi.z, b.z), bx = fminf(bi.w, b.w);
        float ih = fmaxf(by - ty, 0.f), iw = fmaxf(bx - tx, 0.f);
        float inter = ih * iw;
        float iou = inter / (ai + aj - inter + 1e-9f);
        if (iou > 0.7f) bits |= (1ULL << jj);
    }
    g_mask[((size_t)n*PRE_NMS + i)*32 + t] = bits;
}

// ================= K10: greedy scan =================
__global__ __launch_bounds__(32) void scan_kernel(float* __restrict__ out)
{
    const int n = blockIdx.x;
    const int t = threadIdx.x;
    __shared__ unsigned long long rem[32];
    __shared__ unsigned long long kw[32];
    __shared__ int s_flag;
    rem[t] = 0ULL;
    kw[t] = g_keep0[n*32 + t];
    __syncthreads();

    int cnt = 0;
    for (int r = 0; r < PRE_NMS; ++r) {
        if (t == 0) {
            unsigned long long bit = 1ULL << (r & 63);
            s_flag = ((kw[r >> 6] & bit) != 0ULL && (rem[r >> 6] & bit) == 0ULL) ? 1 : 0;
        }
        __syncthreads();
        int f = s_flag;
        __syncthreads();
        if (f) {
            rem[t] |= g_mask[((size_t)n*PRE_NMS + r)*32 + t];
            if (t < 4)
                out[OFF_ROIS + ((size_t)n*POST_NMS + cnt)*4 + t] =
                    g_selbox[((size_t)n*PRE_NMS + r)*4 + t];
            cnt++;
        }
        __syncthreads();
        if (f && cnt == POST_NMS) break;
    }
    for (int idx = cnt*4 + t; idx < POST_NMS*4; idx += 32)
        out[OFF_ROIS + (size_t)n*POST_NMS*4 + idx] = 0.f;
    for (int idx = t; idx < POST_NMS; idx += 32)
        out[OFF_IND + (size_t)n*POST_NMS + idx] = (float)n;
}

// ================= launch =================
extern "C" void kernel_launch(void* const* d_in, const int* in_sizes, int n_in,
                              void* d_out, int out_size)
{
    const float* x  = (const float*)d_in[0];
    const float* w1 = (const float*)d_in[1];
    const float* b1 = (const float*)d_in[2];
    const float* sw = (const float*)d_in[3];
    const float* sb = (const float*)d_in[4];
    const float* lw = (const float*)d_in[5];
    const float* lb = (const float*)d_in[6];
    float* out = (float*)d_out;

    cudaFuncSetAttribute(conv3x3_mma_kernel,
                         cudaFuncAttributeMaxDynamicSharedMemorySize, SMEM_MMA_TOTAL);

    split_w_kernel<<<512, 512>>>(w1);
    prep_wg_kernel<<<KTOT, 256>>>(w1);
    split_x_kernel<<<dim3(8, 64, NB), 256>>>(x);
    conv3x3_mma_kernel<<<dim3(32, 8, NB), 256, SMEM_MMA_TOTAL>>>(b1);
    conv1x1_kernel<<<dim3(64, NB), 256>>>(sw, sb, lw, lb);
    boxes_kernel<<<dim3((NANC + 255) / 256, NB), 256>>>(out);
    cand_kernel<<<NB, 1024>>>();
    gather_kernel<<<dim3(KTOT, NB), 256>>>(x);
    rescore_gemm_kernel<<<dim3(CAND_MAX/RS_PX, 8, NB), 256>>>(b1);
    rescore_anchor_kernel<<<dim3((NANC + 255) / 256, NB), 256>>>(sw, sb, lw, lb);
    topk_kernel<<<NB, 1024>>>();
    nms_mask_kernel<<<dim3(PRE_NMS / 16, NB), dim3(32, 16)>>>();
    scan_kernel<<<NB, 32>>>(out);
}

// round 16
// speedup vs baseline: 1.1709x; 1.1302x over previous
#include <cuda_runtime.h>
#include <cuda_bf16.h>
#include <math.h>
#include <stdint.h>

// ---------------- problem constants ----------------
#define NB      8
#define CIN     512
#define HH      64
#define WW      64
#define OC      512
#define NA      9
#define NANC    (HH*WW*NA)  // 36864
#define PRE_NMS 2000
#define POST_NMS 300
#define CAND_MAX 2048
#define CAND_RANK 2047
#define KTOT 4608           // 9 taps x 512 ic, R3 k-order
#define RS_PX 64            // rescore GEMM pixel tile (R13 proven shape)

#define OFF_LOCS   0
#define OFF_SCORES (NB*NANC*4)
#define OFF_ROIS   (OFF_SCORES + NB*NANC*2)
#define OFF_IND    (OFF_ROIS + NB*POST_NMS*4)
#define OFF_ANC    (OFF_IND + NB*POST_NMS)

// ---------------- scratch ----------------
__device__ float g_h[NB*OC*HH*WW];
__device__ float g_score[NB*18*HH*WW];
__device__ float g_loc[NB*36*HH*WW];
__device__ float g_boxes[NB*NANC*4];
__device__ unsigned long long g_key[NB*NANC];
__device__ float g_selbox[NB*PRE_NMS*4];
__device__ unsigned long long g_keep0[NB*32];
__device__ unsigned long long g_mask[(size_t)NB*PRE_NMS*32];

// bf16 2-way splits (approx conv): x channel-last [s][n][y][x][ic], w [s][tap][oc][ic]
__device__ __align__(16) __nv_bfloat16 g_xs[(size_t)2*NB*64*64*512];
__device__ __align__(16) __nv_bfloat16 g_ws[(size_t)2*9*512*512];

// exact-rescore scratch
__device__ __align__(16) float g_wg[(size_t)KTOT*512];                 // [k][oc]
__device__ __align__(16) float g_gather[(size_t)NB*KTOT*CAND_MAX];    // [n][k][slot]
__device__ __align__(16) float g_hex[(size_t)NB*CAND_MAX*512];        // [n][slot][oc]
__device__ unsigned long long g_tcand[NB];
__device__ int g_npx[NB];
__device__ unsigned short g_plist[NB*4096];
__device__ short g_pixslot[NB*4096];

// ---------------- helpers ----------------
__device__ __forceinline__ uint32_t smem_u32(const void* p) {
    uint32_t a;
    asm("{ .reg .u64 t; cvta.to.shared.u64 t, %1; cvt.u32.u64 %0, t; }" : "=r"(a) : "l"(p));
    return a;
}
#define SWZ(o) ((o) ^ (((o) >> 3) & 0x70))

__device__ __forceinline__ void cp16(uint32_t dst, const void* src, int nbytes) {
    asm volatile("cp.async.cg.shared.global [%0], [%1], 16, %2;"
                 :: "r"(dst), "l"(src), "r"(nbytes) : "memory");
}
#define CP_COMMIT() asm volatile("cp.async.commit_group;" ::: "memory")

__device__ __forceinline__ void ldx4(uint32_t* r, uint32_t addr) {
    asm volatile("ldmatrix.sync.aligned.m8n8.x4.shared.b16 {%0,%1,%2,%3}, [%4];"
                 : "=r"(r[0]), "=r"(r[1]), "=r"(r[2]), "=r"(r[3]) : "r"(addr));
}
__device__ __forceinline__ void mma16816(float* d, const uint32_t* a, uint32_t b0, uint32_t b1) {
    asm volatile("mma.sync.aligned.m16n8k16.row.col.f32.bf16.bf16.f32 "
                 "{%0,%1,%2,%3}, {%4,%5,%6,%7}, {%8,%9}, {%0,%1,%2,%3};"
                 : "+f"(d[0]), "+f"(d[1]), "+f"(d[2]), "+f"(d[3])
                 : "r"(a[0]), "r"(a[1]), "r"(a[2]), "r"(a[3]), "r"(b0), "r"(b1));
}

// ================= prep: split w -> 2x bf16 =================
__global__ __launch_bounds__(512) void split_w_kernel(const float* __restrict__ w)
{
    const int oc = blockIdx.x, ic = threadIdx.x;
    const float* src = w + ((size_t)oc*CIN + ic)*9;
    const size_t ss = (size_t)9*512*512;
#pragma unroll
    for (int t = 0; t < 9; ++t) {
        float v = src[t];
        __nv_bfloat16 b0 = __float2bfloat16_rn(v);
        float r1 = v - __bfloat162float(b0);
        __nv_bfloat16 b1 = __float2bfloat16_rn(r1);
        size_t o = ((size_t)t*512 + oc)*512 + ic;
        g_ws[o] = b0; g_ws[o + ss] = b1;
    }
}

// ================= prep: weights in R3 k-order [k][oc] =================
__global__ __launch_bounds__(256) void prep_wg_kernel(const float* __restrict__ w)
{
    const int k = blockIdx.x;
    const int cc = k / 72, r = k % 72, ici = r / 9, tap = r % 9;
    const int ky = tap / 3, kx = tap % 3, ch = cc*8 + ici;
    for (int oc = threadIdx.x; oc < 512; oc += 256)
        g_wg[(size_t)k*512 + oc] = w[(((size_t)oc*512 + ch)*3 + ky)*3 + kx];
}

// ================= prep: split x -> 2x bf16 channel-last =================
__global__ __launch_bounds__(256) void split_x_kernel(const float* __restrict__ x)
{
    __shared__ float tile[64][65];
    const int c0 = blockIdx.x * 64, y = blockIdx.y, n = blockIdx.z;
    const int t = threadIdx.x;
    {
        int ic = t >> 2, xq = (t & 3) * 16;
        const float4* src = (const float4*)(x + (((size_t)n*CIN + c0 + ic)*64 + y)*64 + xq);
#pragma unroll
        for (int k = 0; k < 4; ++k) {
            float4 v = src[k];
            tile[ic][xq + 4*k + 0] = v.x; tile[ic][xq + 4*k + 1] = v.y;
            tile[ic][xq + 4*k + 2] = v.z; tile[ic][xq + 4*k + 3] = v.w;
        }
    }
    __syncthreads();
    const int xw = t >> 2, ic0 = (t & 3) * 16;
    __align__(16) __nv_bfloat16 o0[16], o1[16];
#pragma unroll
    for (int k = 0; k < 16; ++k) {
        float v = tile[ic0 + k][xw];
        o0[k] = __float2bfloat16_rn(v);
        float r1 = v - __bfloat162float(o0[k]);
        o1[k] = __float2bfloat16_rn(r1);
    }
    const size_t ss = (size_t)NB*64*64*512;
    size_t base = (((size_t)n*64 + y)*64 + xw)*512 + c0 + ic0;
    ((uint4*)(g_xs + base))[0]        = ((uint4*)o0)[0];
    ((uint4*)(g_xs + base))[1]        = ((uint4*)o0)[1];
    ((uint4*)(g_xs + base + ss))[0]   = ((uint4*)o1)[0];
    ((uint4*)(g_xs + base + ss))[1]   = ((uint4*)o1)[1];
}

// ================= K1: approx 3x3 conv via mma.sync bf16 (2-split, 3-product) =================
// CTA: 128 pixels x 64 oc. 8 warps (4 M x 2 N), warp tile 32x32.
// SMEM: 2 buf x 2 splits x (A 16KB + B 8KB) = 96 KB -> 2 CTAs/SM.
#define SMEM_MMA_TOTAL (2*2*16384 + 2*2*8192)

__global__ void __launch_bounds__(256, 2) conv3x3_mma_kernel(const float* __restrict__ bias)
{
    extern __shared__ char smem[];
    const uint32_t sb = smem_u32(smem);
    const int n = blockIdx.z, ntile = blockIdx.y, mtile = blockIdx.x;
    const int y0 = mtile * 2;
    const int tid = threadIdx.x, wid = tid >> 5, lane = tid & 31;
    const int wm = wid & 3, wn = wid >> 2;
    const uint32_t A0 = sb, B0 = sb + 4*16384;

    const int r = tid >> 1, hq = tid & 1;      // A loader: pixel row, 64B half
    const int rb = tid >> 2, qb = tid & 3;     // B loader: oc row, 32B quarter
    const size_t xs_ss = (size_t)NB*64*64*512;
    const size_t ws_ss = (size_t)9*512*512;

    float acc[2][2][8];
#pragma unroll
    for (int a = 0; a < 2; ++a)
#pragma unroll
        for (int b = 0; b < 2; ++b)
#pragma unroll
            for (int c = 0; c < 8; ++c) acc[a][b][c] = 0.f;

    auto issue = [&](int chunk, int buf) {
        const int tap = chunk >> 3, c0 = (chunk & 7) << 6;
        const int ky = tap / 3, kx = tap % 3;
        const int yi = y0 + (r >> 6) + ky - 1;
        const int xi = (r & 63) + kx - 1;
        const bool ok = ((unsigned)yi < 64u) && ((unsigned)xi < 64u);
        const int asz = ok ? 16 : 0;
        const size_t aoff = (((size_t)n*64 + (ok ? yi : 0))*64 + (ok ? xi : 0))*512 + c0 + hq*32;
        const uint32_t bo = (uint32_t)r*128 + (uint32_t)hq*64;
        const size_t boff = ((size_t)tap*512 + (size_t)(ntile*64 + rb))*512 + c0 + qb*16;
        const uint32_t bb = (uint32_t)rb*128 + (uint32_t)qb*32;
#pragma unroll
        for (int s = 0; s < 2; ++s) {
            const char* srcA = (const char*)(g_xs + s*xs_ss + aoff);
            uint32_t dA = A0 + (buf*2 + s)*16384;
            cp16(dA + SWZ(bo +  0), srcA +  0, asz);
            cp16(dA + SWZ(bo + 16), srcA + 16, asz);
            cp16(dA + SWZ(bo + 32), srcA + 32, asz);
            cp16(dA + SWZ(bo + 48), srcA + 48, asz);
            const char* srcB = (const char*)(g_ws + s*ws_ss + boff);
            uint32_t dB = B0 + (buf*2 + s)*8192;
            cp16(dB + SWZ(bb +  0), srcB +  0, 16);
            cp16(dB + SWZ(bb + 16), srcB + 16, 16);
        }
        CP_COMMIT();
    };

    const int g8 = lane >> 3, r8 = lane & 7;
    const int a_row = wm*32 + (g8 & 1)*8 + r8;      // + mt*16
    const int a_kb  = (g8 >> 1)*16;
    const int b_row = wn*32 + (g8 >> 1)*8 + r8;     // + nt*16
    const int b_kb  = (g8 & 1)*16;

    // 3 products: a0b0, a1b0, a0b1 (a1b1 dropped: ~2^-18 relative)
    const int SA[3] = {0, 1, 0};
    const int SB[3] = {0, 0, 1};

    issue(0, 0);

    for (int c = 0; c < 72; ++c) {
        const int buf = c & 1;
        if (c + 1 < 72) {
            issue(c + 1, buf ^ 1);
            asm volatile("cp.async.wait_group 1;" ::: "memory");
        } else {
            asm volatile("cp.async.wait_group 0;" ::: "memory");
        }
        __syncthreads();

        const uint32_t Ab = A0 + buf*2*16384;
        const uint32_t Bb = B0 + buf*2*8192;
#pragma unroll
        for (int ks = 0; ks < 4; ++ks) {
            uint32_t afr[2][2][4];
#pragma unroll
            for (int s = 0; s < 2; ++s)
#pragma unroll
                for (int mt = 0; mt < 2; ++mt)
                    ldx4(afr[s][mt], Ab + s*16384 +
                         (uint32_t)SWZ((a_row + mt*16)*128 + ks*32 + a_kb));
#pragma unroll
            for (int nt = 0; nt < 2; ++nt) {
                uint32_t bfr[2][4];
#pragma unroll
                for (int s = 0; s < 2; ++s)
                    ldx4(bfr[s], Bb + s*8192 +
                         (uint32_t)SWZ((b_row + nt*16)*128 + ks*32 + b_kb));
#pragma unroll
                for (int p = 0; p < 3; ++p) {
                    const int s = SA[p], t = SB[p];
#pragma unroll
                    for (int mt = 0; mt < 2; ++mt) {
                        mma16816(&acc[mt][nt][0], afr[s][mt], bfr[t][0], bfr[t][1]);
                        mma16816(&acc[mt][nt][4], afr[s][mt], bfr[t][2], bfr[t][3]);
                    }
                }
            }
        }
        __syncthreads();
    }

    // epilogue: bias + relu -> g_h [n][oc][y][x]
#pragma unroll
    for (int mt = 0; mt < 2; ++mt) {
        const int pix0 = mtile*128 + wm*32 + mt*16 + (lane >> 2);
#pragma unroll
        for (int nt = 0; nt < 2; ++nt) {
#pragma unroll
            for (int h8 = 0; h8 < 2; ++h8) {
                const int oc = ntile*64 + wn*32 + nt*16 + h8*8 + (lane & 3)*2;
                const float b0 = __ldg(bias + oc), b1 = __ldg(bias + oc + 1);
#pragma unroll
                for (int rr = 0; rr < 2; ++rr) {
                    const int pix = pix0 + rr*8;
                    const int y = pix >> 6, xw = pix & 63;
                    float v0 = acc[mt][nt][h8*4 + rr*2 + 0] + b0;
                    float v1 = acc[mt][nt][h8*4 + rr*2 + 1] + b1;
                    g_h[(((size_t)n*OC + oc    )*64 + y)*64 + xw] = fmaxf(v0, 0.f);
                    g_h[(((size_t)n*OC + oc + 1)*64 + y)*64 + xw] = fmaxf(v1, 0.f);
                }
            }
        }
    }
}

// ================= K2: approx 1x1 convs =================
__global__ __launch_bounds__(256) void conv1x1_kernel(
    const float* __restrict__ sw, const float* __restrict__ sb,
    const float* __restrict__ lw, const float* __restrict__ lb)
{
    const int n = blockIdx.y;
    const int y = blockIdx.x;
    const int tid = threadIdx.x;
    const int xcol = tid & 63;
    const int cg = tid >> 6;

    __shared__ float hs[64][64];
    __shared__ float wsc[56][64];

    float acc[14];
#pragma unroll
    for (int j = 0; j < 14; ++j) acc[j] = 0.f;

    for (int c0 = 0; c0 < CIN; c0 += 64) {
        for (int idx = tid; idx < 64*64; idx += 256) {
            int ic = idx >> 6, xx = idx & 63;
            hs[ic][xx] = g_h[(((size_t)n*OC + c0 + ic)*HH + y)*WW + xx];
        }
        for (int idx = tid; idx < 56*64; idx += 256) {
            int c = idx >> 6, ic = idx & 63;
            float v = 0.f;
            if (c < 18) v = sw[(size_t)c*CIN + c0 + ic];
            else if (c < 54) v = lw[(size_t)(c-18)*CIN + c0 + ic];
            wsc[c][ic] = v;
        }
        __syncthreads();
#pragma unroll 8
        for (int ic = 0; ic < 64; ++ic) {
            float xv = hs[ic][xcol];
#pragma unroll
            for (int j = 0; j < 14; ++j)
                acc[j] = fmaf(wsc[cg + 4*j][ic], xv, acc[j]);
        }
        __syncthreads();
    }
    int p = y * WW + xcol;
#pragma unroll
    for (int j = 0; j < 14; ++j) {
        int c = cg + 4*j;
        if (c < 18)       g_score[((size_t)n*18 + c)*4096 + p] = acc[j] + sb[c];
        else if (c < 54)  g_loc[((size_t)n*36 + (c-18))*4096 + p] = acc[j] + lb[c-18];
    }
}

// ================= K3: approx boxes / keys + full outputs =================
__global__ __launch_bounds__(256) void boxes_kernel(float* __restrict__ out)
{
    const int n = blockIdx.y;
    const int i = blockIdx.x * 256 + threadIdx.x;
    if (i >= NANC) return;
    const int a  = i % NA;
    const int p  = i / NA;
    const int xx = p % WW;
    const int yy = p / WW;

    float s0 = g_score[((size_t)n*18 + 2*a    )*4096 + p];
    float s1 = g_score[((size_t)n*18 + 2*a + 1)*4096 + p];
    out[OFF_SCORES + ((size_t)n*NANC + i)*2 + 0] = s0;
    out[OFF_SCORES + ((size_t)n*NANC + i)*2 + 1] = s1;

    float l0 = g_loc[((size_t)n*36 + a*4 + 0)*4096 + p];
    float l1 = g_loc[((size_t)n*36 + a*4 + 1)*4096 + p];
    float l2 = g_loc[((size_t)n*36 + a*4 + 2)*4096 + p];
    float l3 = g_loc[((size_t)n*36 + a*4 + 3)*4096 + p];
    out[OFF_LOCS + ((size_t)n*NANC + i)*4 + 0] = l0;
    out[OFF_LOCS + ((size_t)n*NANC + i)*4 + 1] = l1;
    out[OFF_LOCS + ((size_t)n*NANC + i)*4 + 2] = l2;
    out[OFF_LOCS + ((size_t)n*NANC + i)*4 + 3] = l3;

    const double ratios[3] = {0.5, 1.0, 2.0};
    const double scales[3] = {8.0, 16.0, 32.0};
    double hh = (16.0 * scales[a % 3]) * sqrt(ratios[a / 3]);
    double wd = (16.0 * scales[a % 3]) * sqrt(1.0 / ratios[a / 3]);
    float ab0 = (float)(8.0 - hh / 2.0);
    float ab1 = (float)(8.0 - wd / 2.0);
    float ab2 = (float)(8.0 + hh / 2.0);
    float ab3 = (float)(8.0 + wd / 2.0);
    float a0 = ab0 + (float)(yy * 16);
    float a1 = ab1 + (float)(xx * 16);
    float a2 = ab2 + (float)(yy * 16);
    float a3 = ab3 + (float)(xx * 16);
    if (n == 0) {
        out[OFF_ANC + (size_t)i*4 + 0] = a0;
        out[OFF_ANC + (size_t)i*4 + 1] = a1;
        out[OFF_ANC + (size_t)i*4 + 2] = a2;
        out[OFF_ANC + (size_t)i*4 + 3] = a3;
    }

    float ha = __fadd_rn(a2, -a0);
    float wa = __fadd_rn(a3, -a1);
    float cy = __fadd_rn(a0, __fmul_rn(0.5f, ha));
    float cx = __fadd_rn(a1, __fmul_rn(0.5f, wa));
    float cy2 = __fadd_rn(__fmul_rn(l0, ha), cy);
    float cx2 = __fadd_rn(__fmul_rn(l1, wa), cx);
    float h2 = __fmul_rn(expf(l2), ha);
    float w2 = __fmul_rn(expf(l3), wa);
    float b0 = __fadd_rn(cy2, -__fmul_rn(0.5f, h2));
    float b1 = __fadd_rn(cx2, -__fmul_rn(0.5f, w2));
    float b2 = __fadd_rn(cy2,  __fmul_rn(0.5f, h2));
    float b3 = __fadd_rn(cx2,  __fmul_rn(0.5f, w2));
    b0 = fminf(fmaxf(b0, 0.f), 1024.f);
    b1 = fminf(fmaxf(b1, 0.f), 1024.f);
    b2 = fminf(fmaxf(b2, 0.f), 1024.f);
    b3 = fminf(fmaxf(b3, 0.f), 1024.f);
    bool valid = ((b2 - b0) >= 16.f) && ((b3 - b1) >= 16.f);

    float m = fmaxf(s0, s1);
    float e0 = expf(s0 - m), e1 = expf(s1 - m);
    float fg = e1 / (e0 + e1);
    if (!valid) fg = -INFINITY;

    float* bp = g_boxes + ((size_t)n*NANC + i)*4;
    bp[0] = b0; bp[1] = b1; bp[2] = b2; bp[3] = b3;

    unsigned int kb = __float_as_uint(fg);
    unsigned int k  = (kb & 0x80000000u) ? ~kb : (kb | 0x80000000u);
    g_key[(size_t)n*NANC + i] =
        ((unsigned long long)k << 16) | (unsigned long long)(65535 - i);
}

// ================= K4: candidate selection (threshold + pixel compaction) =================
__global__ __launch_bounds__(1024) void cand_kernel()
{
    const int n = blockIdx.x;
    const int tid = threadIdx.x;
    const int lane = tid & 31, wid = tid >> 5;
    __shared__ unsigned int hist[256];
    __shared__ unsigned long long s_prefix;
    __shared__ int s_rank;
    __shared__ unsigned char flag[4096];
    __shared__ int wsum[32];

    const unsigned long long* key = g_key + (size_t)n * NANC;
    if (tid == 0) { s_prefix = 0ULL; s_rank = CAND_RANK; }
    __syncthreads();

    for (int d = 5; d >= 0; --d) {
        if (tid < 256) hist[tid] = 0u;
        __syncthreads();
        unsigned long long pref = s_prefix;
        int sh = (d + 1) * 8;
        for (int idx = tid; idx < NANC; idx += 1024) {
            unsigned long long k = key[idx];
            if ((k >> sh) == (pref >> sh))
                atomicAdd(&hist[(unsigned)(k >> (8*d)) & 255u], 1u);
        }
        __syncthreads();
        if (tid == 0) {
            int cum = 0, rank = s_rank;
            for (int v = 255; v >= 0; --v) {
                int c = (int)hist[v];
                if (cum + c > rank) {
                    s_prefix = pref | ((unsigned long long)(unsigned)v << (8*d));
                    s_rank = rank - cum;
                    break;
                }
                cum += c;
            }
        }
        __syncthreads();
    }
    const unsigned long long T = s_prefix;
    if (tid == 0) g_tcand[n] = T;

    for (int p = tid; p < 4096; p += 1024) flag[p] = 0;
    __syncthreads();
    for (int i = tid; i < NANC; i += 1024)
        if (key[i] >= T) flag[i / 9] = 1;
    __syncthreads();

    int have[4], cnt = 0;
#pragma unroll
    for (int j = 0; j < 4; ++j) { have[j] = flag[tid*4 + j]; cnt += have[j]; }
    int incl = cnt;
#pragma unroll
    for (int off = 1; off < 32; off <<= 1) {
        int v = __shfl_up_sync(0xffffffffu, incl, off);
        if (lane >= off) incl += v;
    }
    if (lane == 31) wsum[wid] = incl;
    __syncthreads();
    if (wid == 0) {
        int v = wsum[lane];
        int inc2 = v;
#pragma unroll
        for (int off = 1; off < 32; off <<= 1) {
            int u = __shfl_up_sync(0xffffffffu, inc2, off);
            if (lane >= off) inc2 += u;
        }
        wsum[lane] = inc2 - v;   // exclusive
    }
    __syncthreads();
    int base = wsum[wid] + (incl - cnt);
    int run = 0;
#pragma unroll
    for (int j = 0; j < 4; ++j) {
        int p = tid*4 + j;
        if (have[j]) {
            int s = base + run; run++;
            g_plist[n*4096 + s] = (unsigned short)p;
            g_pixslot[n*4096 + p] = (short)s;
        } else {
            g_pixslot[n*4096 + p] = -1;
        }
    }
    if (tid == 1023) g_npx[n] = base + cnt;
}

// ================= K5: gather candidate im2col x in R3 k-order [n][k][slot] =================
__global__ __launch_bounds__(256) void gather_kernel(const float* __restrict__ x)
{
    const int n = blockIdx.y, k = blockIdx.x;
    const int cc = k / 72, r = k % 72, ici = r / 9, tap = r % 9;
    const int ky = tap / 3, kx = tap % 3, ch = cc*8 + ici;
    const int npx = g_npx[n];
    int lim = (npx + RS_PX - 1) & ~(RS_PX - 1);
    if (lim > CAND_MAX) lim = CAND_MAX;
    for (int s = threadIdx.x; s < lim; s += 256) {
        float v = 0.f;
        if (s < npx) {
            int pix = g_plist[n*4096 + s];
            int y = pix >> 6, xx = pix & 63;
            int yi = y + ky - 1, xi = xx + kx - 1;
            if ((unsigned)yi < 64u && (unsigned)xi < 64u)
                v = x[(((size_t)n*512 + ch)*64 + yi)*64 + xi];
        }
        g_gather[((size_t)n*KTOT + k)*CAND_MAX + s] = v;
    }
}

// ================= K6: exact rescore GEMM — bit-exact R3 fmaf chains =================
// R13's proven 64px x 64oc tile (conflict-free LDS), k-tile deepened 32->64 to halve
// sync/loop overhead. Sequential k 0..4607 per output, identical fmaf order.
// SMEM: 2 buf x (xs 16KB + ws 16KB) = 64KB; __launch_bounds__(256,2), ~80 regs, no spills.
__global__ void __launch_bounds__(256, 2) rescore_gemm_kernel(const float* __restrict__ bias)
{
    __shared__ float xs[2][64][64];
    __shared__ float ws[2][64][64];
    const int sblk = blockIdx.x, ob = blockIdx.y, n = blockIdx.z;
    if (sblk * RS_PX >= g_npx[n]) return;
    const int tid = threadIdx.x;
    const int pq = tid & 15, oq = tid >> 4;
    const size_t gbase = (size_t)n*KTOT*CAND_MAX + (size_t)sblk*RS_PX;

    float acc[4][4];
#pragma unroll
    for (int i = 0; i < 4; ++i)
#pragma unroll
        for (int j = 0; j < 4; ++j) acc[i][j] = 0.f;

    // preload kt=0: 64 rows of each
#pragma unroll
    for (int q = 0; q < 4; ++q) {
        int f = tid + q*256, row = f >> 4, c4 = f & 15;
        *(float4*)&xs[0][row][c4*4] =
            *(const float4*)(g_gather + gbase + (size_t)row*CAND_MAX + c4*4);
        *(float4*)&ws[0][row][c4*4] =
            *(const float4*)(g_wg + (size_t)row*512 + ob*64 + c4*4);
    }
    __syncthreads();
    int buf = 0;

    for (int kt = 0; kt < 72; ++kt) {
        float4 rx[4], rw[4];
        if (kt < 71) {
            const int k1 = (kt + 1) * 64;
#pragma unroll
            for (int q = 0; q < 4; ++q) {
                int f = tid + q*256, row = f >> 4, c4 = f & 15;
                rx[q] = *(const float4*)(g_gather + gbase + (size_t)(k1 + row)*CAND_MAX + c4*4);
                rw[q] = *(const float4*)(g_wg + (size_t)(k1 + row)*512 + ob*64 + c4*4);
            }
        }
#pragma unroll 16
        for (int kk = 0; kk < 64; ++kk) {
            float4 xv = *(float4*)&xs[buf][kk][pq*4];
            float4 wv = *(float4*)&ws[buf][kk][oq*4];
            float xa[4] = {xv.x, xv.y, xv.z, xv.w};
            float wa[4] = {wv.x, wv.y, wv.z, wv.w};
#pragma unroll
            for (int i = 0; i < 4; ++i)
#pragma unroll
                for (int j = 0; j < 4; ++j)
                    acc[i][j] = __fmaf_rn(wa[j], xa[i], acc[i][j]);
        }
        if (kt < 71) {
            __syncthreads();
#pragma unroll
            for (int q = 0; q < 4; ++q) {
                int f = tid + q*256, row = f >> 4, c4 = f & 15;
                *(float4*)&xs[buf ^ 1][row][c4*4] = rx[q];
                *(float4*)&ws[buf ^ 1][row][c4*4] = rw[q];
            }
            __syncthreads();
            buf ^= 1;
        }
    }

    float bv[4];
#pragma unroll
    for (int j = 0; j < 4; ++j) bv[j] = __ldg(bias + ob*64 + oq*4 + j);
#pragma unroll
    for (int i = 0; i < 4; ++i) {
        int slot = sblk*RS_PX + pq*4 + i;
        float4 o;
        o.x = fmaxf(__fadd_rn(acc[i][0], bv[0]), 0.f);
        o.y = fmaxf(__fadd_rn(acc[i][1], bv[1]), 0.f);
        o.z = fmaxf(__fadd_rn(acc[i][2], bv[2]), 0.f);
        o.w = fmaxf(__fadd_rn(acc[i][3], bv[3]), 0.f);
        *(float4*)(g_hex + ((size_t)n*CAND_MAX + slot)*512 + ob*64 + oq*4) = o;
    }
}

// ================= K7: exact per-anchor score/loc/key/box (R3 conv1x1 order) =================
__global__ __launch_bounds__(256) void rescore_anchor_kernel(
    const float* __restrict__ sw, const float* __restrict__ sb,
    const float* __restrict__ lw, const float* __restrict__ lb)
{
    const int n = blockIdx.y;
    const int i = blockIdx.x * 256 + threadIdx.x;
    if (i >= NANC) return;
    if (g_key[(size_t)n*NANC + i] < g_tcand[n]) return;
    const int a = i % NA, p = i / NA;
    const int slot = g_pixslot[n*4096 + p];
    if (slot < 0) return;
    const float* h = g_hex + ((size_t)n*CAND_MAX + slot)*512;
    const float* w0 = sw + (size_t)(2*a)*512;
    const float* w1 = sw + (size_t)(2*a + 1)*512;
    const float* wl0 = lw + (size_t)(4*a + 0)*512;
    const float* wl1 = lw + (size_t)(4*a + 1)*512;
    const float* wl2 = lw + (size_t)(4*a + 2)*512;
    const float* wl3 = lw + (size_t)(4*a + 3)*512;

    float s0 = 0.f, s1 = 0.f, l0 = 0.f, l1 = 0.f, l2 = 0.f, l3 = 0.f;
    for (int ic = 0; ic < 512; ic += 4) {
        float4 hv = *(const float4*)(h + ic);
        float ha[4] = {hv.x, hv.y, hv.z, hv.w};
#pragma unroll
        for (int q = 0; q < 4; ++q) {
            float hq = ha[q];
            s0 = __fmaf_rn(__ldg(w0 + ic + q), hq, s0);
            s1 = __fmaf_rn(__ldg(w1 + ic + q), hq, s1);
            l0 = __fmaf_rn(__ldg(wl0 + ic + q), hq, l0);
            l1 = __fmaf_rn(__ldg(wl1 + ic + q), hq, l1);
            l2 = __fmaf_rn(__ldg(wl2 + ic + q), hq, l2);
            l3 = __fmaf_rn(__ldg(wl3 + ic + q), hq, l3);
        }
    }
    s0 = __fadd_rn(s0, __ldg(sb + 2*a));
    s1 = __fadd_rn(s1, __ldg(sb + 2*a + 1));
    l0 = __fadd_rn(l0, __ldg(lb + 4*a + 0));
    l1 = __fadd_rn(l1, __ldg(lb + 4*a + 1));
    l2 = __fadd_rn(l2, __ldg(lb + 4*a + 2));
    l3 = __fadd_rn(l3, __ldg(lb + 4*a + 3));

    const int xx = p % WW, yy = p / WW;
    const double ratios[3] = {0.5, 1.0, 2.0};
    const double scales[3] = {8.0, 16.0, 32.0};
    double hh = (16.0 * scales[a % 3]) * sqrt(ratios[a / 3]);
    double wd = (16.0 * scales[a % 3]) * sqrt(1.0 / ratios[a / 3]);
    float a0 = (float)(8.0 - hh / 2.0) + (float)(yy * 16);
    float a1 = (float)(8.0 - wd / 2.0) + (float)(xx * 16);
    float a2 = (float)(8.0 + hh / 2.0) + (float)(yy * 16);
    float a3 = (float)(8.0 + wd / 2.0) + (float)(xx * 16);

    float haa = __fadd_rn(a2, -a0);
    float waa = __fadd_rn(a3, -a1);
    float cy = __fadd_rn(a0, __fmul_rn(0.5f, haa));
    float cx = __fadd_rn(a1, __fmul_rn(0.5f, waa));
    float cy2 = __fadd_rn(__fmul_rn(l0, haa), cy);
    float cx2 = __fadd_rn(__fmul_rn(l1, waa), cx);
    float h2 = __fmul_rn(expf(l2), haa);
    float w2 = __fmul_rn(expf(l3), waa);
    float b0 = __fadd_rn(cy2, -__fmul_rn(0.5f, h2));
    float b1 = __fadd_rn(cx2, -__fmul_rn(0.5f, w2));
    float b2 = __fadd_rn(cy2,  __fmul_rn(0.5f, h2));
    float b3 = __fadd_rn(cx2,  __fmul_rn(0.5f, w2));
    b0 = fminf(fmaxf(b0, 0.f), 1024.f);
    b1 = fminf(fmaxf(b1, 0.f), 1024.f);
    b2 = fminf(fmaxf(b2, 0.f), 1024.f);
    b3 = fminf(fmaxf(b3, 0.f), 1024.f);
    bool valid = ((b2 - b0) >= 16.f) && ((b3 - b1) >= 16.f);

    float m = fmaxf(s0, s1);
    float e0 = expf(s0 - m), e1 = expf(s1 - m);
    float fg = e1 / (e0 + e1);
    if (!valid) fg = -INFINITY;

    float* bp = g_boxes + ((size_t)n*NANC + i)*4;
    bp[0] = b0; bp[1] = b1; bp[2] = b2; bp[3] = b3;

    unsigned int kb = __float_as_uint(fg);
    unsigned int k  = (kb & 0x80000000u) ? ~kb : (kb | 0x80000000u);
    g_key[(size_t)n*NANC + i] =
        ((unsigned long long)k << 16) | (unsigned long long)(65535 - i);
}

// ================= K8: exact top-2000 =================
__global__ __launch_bounds__(1024) void topk_kernel()
{
    const int n = blockIdx.x;
    const int tid = threadIdx.x;
    __shared__ unsigned int hist[256];
    __shared__ unsigned long long ssort[2048];
    __shared__ unsigned long long s_prefix;
    __shared__ int s_rank;
    __shared__ int s_cnt;

    const unsigned long long* key = g_key + (size_t)n * NANC;
    if (tid == 0) { s_prefix = 0ULL; s_rank = PRE_NMS - 1; s_cnt = 0; }
    if (tid < 32) g_keep0[n*32 + tid] = 0ULL;
    __syncthreads();

    for (int d = 5; d >= 0; --d) {
        if (tid < 256) hist[tid] = 0u;
        __syncthreads();
        unsigned long long pref = s_prefix;
        int sh = (d + 1) * 8;
        for (int idx = tid; idx < NANC; idx += 1024) {
            unsigned long long k = key[idx];
            if ((k >> sh) == (pref >> sh))
                atomicAdd(&hist[(unsigned)(k >> (8*d)) & 255u], 1u);
        }
        __syncthreads();
        if (tid == 0) {
            int cum = 0, rank = s_rank;
            for (int v = 255; v >= 0; --v) {
                int c = (int)hist[v];
                if (cum + c > rank) {
                    s_prefix = pref | ((unsigned long long)(unsigned)v << (8*d));
                    s_rank = rank - cum;
                    break;
                }
                cum += c;
            }
        }
        __syncthreads();
    }
    unsigned long long T = s_prefix;
    __syncthreads();
    for (int idx = tid; idx < NANC; idx += 1024) {
        unsigned long long k = key[idx];
        if (k >= T) {
            int pos = atomicAdd(&s_cnt, 1);
            if (pos < 2048) ssort[pos] = k;
        }
    }
    __syncthreads();
    int cnt = s_cnt;
    for (int idx = cnt + tid; idx < 2048; idx += 1024) ssort[idx] = 0ULL;
    __syncthreads();

    for (int ksz = 2; ksz <= 2048; ksz <<= 1) {
        for (int j = ksz >> 1; j > 0; j >>= 1) {
            for (int idx = tid; idx < 2048; idx += 1024) {
                int ixj = idx ^ j;
                if (ixj > idx) {
                    unsigned long long va = ssort[idx], vb = ssort[ixj];
                    bool desc = ((idx & ksz) == 0);
                    if (desc ? (va < vb) : (va > vb)) { ssort[idx] = vb; ssort[ixj] = va; }
                }
            }
            __syncthreads();
        }
    }

    for (int r = tid; r < PRE_NMS; r += 1024) {
        unsigned long long comp = ssort[r];
        int idx = 65535 - (int)(comp & 0xFFFFULL);
        const float4 bv = *reinterpret_cast<const float4*>(g_boxes + ((size_t)n*NANC + idx)*4);
        *reinterpret_cast<float4*>(g_selbox + ((size_t)n*PRE_NMS + r)*4) = bv;
        unsigned int fk = (unsigned)(comp >> 16);
        if (fk > 0x007FFFFFu)
            atomicOr(&g_keep0[n*32 + (r >> 6)], 1ULL << (r & 63));
    }
}

// ================= K9: NMS mask =================
__global__ __launch_bounds__(512) void nms_mask_kernel()
{
    const int n = blockIdx.y;
    const int i = blockIdx.x * 16 + threadIdx.y;
    const int t = threadIdx.x;
    __shared__ float4 bj[PRE_NMS];
    int ftid = threadIdx.y * 32 + threadIdx.x;
    for (int idx = ftid; idx < PRE_NMS; idx += 512)
        bj[idx] = *reinterpret_cast<const float4*>(g_selbox + ((size_t)n*PRE_NMS + idx)*4);
    __syncthreads();

    float4 bi = bj[i];
    float ai = (bi.z - bi.x) * (bi.w - bi.y);
    unsigned long long bits = 0ULL;
    int jbase = t << 6;
#pragma unroll 4
    for (int jj = 0; jj < 64; ++jj) {
        int j = jbase + jj;
        if (j >= PRE_NMS) break;
        if (j <= i) continue;
        float4 b = bj[j];
        float aj = (b.z - b.x) * (b.w - b.y);
        float ty = fmaxf(bi.x, b.x), tx = fmaxf(bi.y, b.y);
        float by = fminf(bi.z, b.z), bx = fminf(bi.w, b.w);
        float ih = fmaxf(by - ty, 0.f), iw = fmaxf(bx - tx, 0.f);
        float inter = ih * iw;
        float iou = inter / (ai + aj - inter + 1e-9f);
        if (iou > 0.7f) bits |= (1ULL << jj);
    }
    g_mask[((size_t)n*PRE_NMS + i)*32 + t] = bits;
}

// ================= K10: greedy scan =================
__global__ __launch_bounds__(32) void scan_kernel(float* __restrict__ out)
{
    const int n = blockIdx.x;
    const int t = threadIdx.x;
    __shared__ unsigned long long rem[32];
    __shared__ unsigned long long kw[32];
    __shared__ int s_flag;
    rem[t] = 0ULL;
    kw[t] = g_keep0[n*32 + t];
    __syncthreads();

    int cnt = 0;
    for (int r = 0; r < PRE_NMS; ++r) {
        if (t == 0) {
            unsigned long long bit = 1ULL << (r & 63);
            s_flag = ((kw[r >> 6] & bit) != 0ULL && (rem[r >> 6] & bit) == 0ULL) ? 1 : 0;
        }
        __syncthreads();
        int f = s_flag;
        __syncthreads();
        if (f) {
            rem[t] |= g_mask[((size_t)n*PRE_NMS + r)*32 + t];
            if (t < 4)
                out[OFF_ROIS + ((size_t)n*POST_NMS + cnt)*4 + t] =
                    g_selbox[((size_t)n*PRE_NMS + r)*4 + t];
            cnt++;
        }
        __syncthreads();
        if (f && cnt == POST_NMS) break;
    }
    for (int idx = cnt*4 + t; idx < POST_NMS*4; idx += 32)
        out[OFF_ROIS + (size_t)n*POST_NMS*4 + idx] = 0.f;
    for (int idx = t; idx < POST_NMS; idx += 32)
        out[OFF_IND + (size_t)n*POST_NMS + idx] = (float)n;
}

// ================= launch =================
extern "C" void kernel_launch(void* const* d_in, const int* in_sizes, int n_in,
                              void* d_out, int out_size)
{
    const float* x  = (const float*)d_in[0];
    const float* w1 = (const float*)d_in[1];
    const float* b1 = (const float*)d_in[2];
    const float* sw = (const float*)d_in[3];
    const float* sb = (const float*)d_in[4];
    const float* lw = (const float*)d_in[5];
    const float* lb = (const float*)d_in[6];
    float* out = (float*)d_out;

    cudaFuncSetAttribute(conv3x3_mma_kernel,
                         cudaFuncAttributeMaxDynamicSharedMemorySize, SMEM_MMA_TOTAL);

    split_w_kernel<<<512, 512>>>(w1);
    prep_wg_kernel<<<KTOT, 256>>>(w1);
    split_x_kernel<<<dim3(8, 64, NB), 256>>>(x);
    conv3x3_mma_kernel<<<dim3(32, 8, NB), 256, SMEM_MMA_TOTAL>>>(b1);
    conv1x1_kernel<<<dim3(64, NB), 256>>>(sw, sb, lw, lb);
    boxes_kernel<<<dim3((NANC + 255) / 256, NB), 256>>>(out);
    cand_kernel<<<NB, 1024>>>();
    gather_kernel<<<dim3(KTOT, NB), 256>>>(x);
    rescore_gemm_kernel<<<dim3(CAND_MAX/RS_PX, 8, NB), 256>>>(b1);
    rescore_anchor_kernel<<<dim3((NANC + 255) / 256, NB), 256>>>(sw, sb, lw, lb);
    topk_kernel<<<NB, 1024>>>();
    nms_mask_kernel<<<dim3(PRE_NMS / 16, NB), dim3(32, 16)>>>();
    scan_kernel<<<NB, 32>>>(out);
}

// round 17
// speedup vs baseline: 1.2332x; 1.0533x over previous
#include <cuda_runtime.h>
#include <cuda_bf16.h>
#include <math.h>
#include <stdint.h>

// ---------------- problem constants ----------------
#define NB      8
#define NBH     4           // images per stream half
#define CIN     512
#define HH      64
#define WW      64
#define OC      512
#define NA      9
#define NANC    (HH*WW*NA)  // 36864
#define PRE_NMS 2000
#define POST_NMS 300
#define CAND_MAX 2048
#define CAND_RANK 2047
#define KTOT 4608           // 9 taps x 512 ic, R3 k-order
#define RS_PX 64            // rescore GEMM pixel tile (R13 proven shape)

#define OFF_LOCS   0
#define OFF_SCORES (NB*NANC*4)
#define OFF_ROIS   (OFF_SCORES + NB*NANC*2)
#define OFF_IND    (OFF_ROIS + NB*POST_NMS*4)
#define OFF_ANC    (OFF_IND + NB*POST_NMS)

// ---------------- scratch ----------------
__device__ float g_h[NB*OC*HH*WW];
__device__ float g_score[NB*18*HH*WW];
__device__ float g_loc[NB*36*HH*WW];
__device__ float g_boxes[NB*NANC*4];
__device__ unsigned long long g_key[NB*NANC];
__device__ float g_selbox[NB*PRE_NMS*4];
__device__ unsigned long long g_keep0[NB*32];
__device__ unsigned long long g_mask[(size_t)NB*PRE_NMS*32];

// bf16 2-way splits (approx conv): x channel-last [s][n][y][x][ic], w [s][tap][oc][ic]
__device__ __align__(16) __nv_bfloat16 g_xs[(size_t)2*NB*64*64*512];
__device__ __align__(16) __nv_bfloat16 g_ws[(size_t)2*9*512*512];

// exact-rescore scratch
__device__ __align__(16) float g_wg[(size_t)KTOT*512];                 // [k][oc]
__device__ __align__(16) float g_gather[(size_t)NB*KTOT*CAND_MAX];    // [n][k][slot]
__device__ __align__(16) float g_hex[(size_t)NB*CAND_MAX*512];        // [n][slot][oc]
__device__ unsigned long long g_tcand[NB];
__device__ int g_npx[NB];
__device__ unsigned short g_plist[NB*4096];
__device__ short g_pixslot[NB*4096];

// ---------------- helpers ----------------
__device__ __forceinline__ uint32_t smem_u32(const void* p) {
    uint32_t a;
    asm("{ .reg .u64 t; cvta.to.shared.u64 t, %1; cvt.u32.u64 %0, t; }" : "=r"(a) : "l"(p));
    return a;
}
#define SWZ(o) ((o) ^ (((o) >> 3) & 0x70))

__device__ __forceinline__ void cp16(uint32_t dst, const void* src, int nbytes) {
    asm volatile("cp.async.cg.shared.global [%0], [%1], 16, %2;"
                 :: "r"(dst), "l"(src), "r"(nbytes) : "memory");
}
#define CP_COMMIT() asm volatile("cp.async.commit_group;" ::: "memory")

__device__ __forceinline__ void ldx4(uint32_t* r, uint32_t addr) {
    asm volatile("ldmatrix.sync.aligned.m8n8.x4.shared.b16 {%0,%1,%2,%3}, [%4];"
                 : "=r"(r[0]), "=r"(r[1]), "=r"(r[2]), "=r"(r[3]) : "r"(addr));
}
__device__ __forceinline__ void mma16816(float* d, const uint32_t* a, uint32_t b0, uint32_t b1) {
    asm volatile("mma.sync.aligned.m16n8k16.row.col.f32.bf16.bf16.f32 "
                 "{%0,%1,%2,%3}, {%4,%5,%6,%7}, {%8,%9}, {%0,%1,%2,%3};"
                 : "+f"(d[0]), "+f"(d[1]), "+f"(d[2]), "+f"(d[3])
                 : "r"(a[0]), "r"(a[1]), "r"(a[2]), "r"(a[3]), "r"(b0), "r"(b1));
}

// ================= prep: split w -> 2x bf16 =================
__global__ __launch_bounds__(512) void split_w_kernel(const float* __restrict__ w)
{
    const int oc = blockIdx.x, ic = threadIdx.x;
    const float* src = w + ((size_t)oc*CIN + ic)*9;
    const size_t ss = (size_t)9*512*512;
#pragma unroll
    for (int t = 0; t < 9; ++t) {
        float v = src[t];
        __nv_bfloat16 b0 = __float2bfloat16_rn(v);
        float r1 = v - __bfloat162float(b0);
        __nv_bfloat16 b1 = __float2bfloat16_rn(r1);
        size_t o = ((size_t)t*512 + oc)*512 + ic;
        g_ws[o] = b0; g_ws[o + ss] = b1;
    }
}

// ================= prep: weights in R3 k-order [k][oc] =================
__global__ __launch_bounds__(256) void prep_wg_kernel(const float* __restrict__ w)
{
    const int k = blockIdx.x;
    const int cc = k / 72, r = k % 72, ici = r / 9, tap = r % 9;
    const int ky = tap / 3, kx = tap % 3, ch = cc*8 + ici;
    for (int oc = threadIdx.x; oc < 512; oc += 256)
        g_wg[(size_t)k*512 + oc] = w[(((size_t)oc*512 + ch)*3 + ky)*3 + kx];
}

// ================= prep: split x -> 2x bf16 channel-last =================
__global__ __launch_bounds__(256) void split_x_kernel(const float* __restrict__ x, int n0)
{
    __shared__ float tile[64][65];
    const int c0 = blockIdx.x * 64, y = blockIdx.y, n = n0 + blockIdx.z;
    const int t = threadIdx.x;
    {
        int ic = t >> 2, xq = (t & 3) * 16;
        const float4* src = (const float4*)(x + (((size_t)n*CIN + c0 + ic)*64 + y)*64 + xq);
#pragma unroll
        for (int k = 0; k < 4; ++k) {
            float4 v = src[k];
            tile[ic][xq + 4*k + 0] = v.x; tile[ic][xq + 4*k + 1] = v.y;
            tile[ic][xq + 4*k + 2] = v.z; tile[ic][xq + 4*k + 3] = v.w;
        }
    }
    __syncthreads();
    const int xw = t >> 2, ic0 = (t & 3) * 16;
    __align__(16) __nv_bfloat16 o0[16], o1[16];
#pragma unroll
    for (int k = 0; k < 16; ++k) {
        float v = tile[ic0 + k][xw];
        o0[k] = __float2bfloat16_rn(v);
        float r1 = v - __bfloat162float(o0[k]);
        o1[k] = __float2bfloat16_rn(r1);
    }
    const size_t ss = (size_t)NB*64*64*512;
    size_t base = (((size_t)n*64 + y)*64 + xw)*512 + c0 + ic0;
    ((uint4*)(g_xs + base))[0]        = ((uint4*)o0)[0];
    ((uint4*)(g_xs + base))[1]        = ((uint4*)o0)[1];
    ((uint4*)(g_xs + base + ss))[0]   = ((uint4*)o1)[0];
    ((uint4*)(g_xs + base + ss))[1]   = ((uint4*)o1)[1];
}

// ================= K1: approx 3x3 conv via mma.sync bf16 (2-split, 3-product) =================
// CTA: 128 pixels x 64 oc. 8 warps (4 M x 2 N), warp tile 32x32.
// SMEM: 2 buf x 2 splits x (A 16KB + B 8KB) = 96 KB -> 2 CTAs/SM.
#define SMEM_MMA_TOTAL (2*2*16384 + 2*2*8192)

__global__ void __launch_bounds__(256, 2) conv3x3_mma_kernel(const float* __restrict__ bias, int n0)
{
    extern __shared__ char smem[];
    const uint32_t sb = smem_u32(smem);
    const int n = n0 + blockIdx.z, ntile = blockIdx.y, mtile = blockIdx.x;
    const int y0 = mtile * 2;
    const int tid = threadIdx.x, wid = tid >> 5, lane = tid & 31;
    const int wm = wid & 3, wn = wid >> 2;
    const uint32_t A0 = sb, B0 = sb + 4*16384;

    const int r = tid >> 1, hq = tid & 1;      // A loader: pixel row, 64B half
    const int rb = tid >> 2, qb = tid & 3;     // B loader: oc row, 32B quarter
    const size_t xs_ss = (size_t)NB*64*64*512;
    const size_t ws_ss = (size_t)9*512*512;

    float acc[2][2][8];
#pragma unroll
    for (int a = 0; a < 2; ++a)
#pragma unroll
        for (int b = 0; b < 2; ++b)
#pragma unroll
            for (int c = 0; c < 8; ++c) acc[a][b][c] = 0.f;

    auto issue = [&](int chunk, int buf) {
        const int tap = chunk >> 3, c0 = (chunk & 7) << 6;
        const int ky = tap / 3, kx = tap % 3;
        const int yi = y0 + (r >> 6) + ky - 1;
        const int xi = (r & 63) + kx - 1;
        const bool ok = ((unsigned)yi < 64u) && ((unsigned)xi < 64u);
        const int asz = ok ? 16 : 0;
        const size_t aoff = (((size_t)n*64 + (ok ? yi : 0))*64 + (ok ? xi : 0))*512 + c0 + hq*32;
        const uint32_t bo = (uint32_t)r*128 + (uint32_t)hq*64;
        const size_t boff = ((size_t)tap*512 + (size_t)(ntile*64 + rb))*512 + c0 + qb*16;
        const uint32_t bb = (uint32_t)rb*128 + (uint32_t)qb*32;
#pragma unroll
        for (int s = 0; s < 2; ++s) {
            const char* srcA = (const char*)(g_xs + s*xs_ss + aoff);
            uint32_t dA = A0 + (buf*2 + s)*16384;
            cp16(dA + SWZ(bo +  0), srcA +  0, asz);
            cp16(dA + SWZ(bo + 16), srcA + 16, asz);
            cp16(dA + SWZ(bo + 32), srcA + 32, asz);
            cp16(dA + SWZ(bo + 48), srcA + 48, asz);
            const char* srcB = (const char*)(g_ws + s*ws_ss + boff);
            uint32_t dB = B0 + (buf*2 + s)*8192;
            cp16(dB + SWZ(bb +  0), srcB +  0, 16);
            cp16(dB + SWZ(bb + 16), srcB + 16, 16);
        }
        CP_COMMIT();
    };

    const int g8 = lane >> 3, r8 = lane & 7;
    const int a_row = wm*32 + (g8 & 1)*8 + r8;      // + mt*16
    const int a_kb  = (g8 >> 1)*16;
    const int b_row = wn*32 + (g8 >> 1)*8 + r8;     // + nt*16
    const int b_kb  = (g8 & 1)*16;

    // 3 products: a0b0, a1b0, a0b1 (a1b1 dropped: ~2^-18 relative)
    const int SA[3] = {0, 1, 0};
    const int SB[3] = {0, 0, 1};

    issue(0, 0);

    for (int c = 0; c < 72; ++c) {
        const int buf = c & 1;
        if (c + 1 < 72) {
            issue(c + 1, buf ^ 1);
            asm volatile("cp.async.wait_group 1;" ::: "memory");
        } else {
            asm volatile("cp.async.wait_group 0;" ::: "memory");
        }
        __syncthreads();

        const uint32_t Ab = A0 + buf*2*16384;
        const uint32_t Bb = B0 + buf*2*8192;
#pragma unroll
        for (int ks = 0; ks < 4; ++ks) {
            uint32_t afr[2][2][4];
#pragma unroll
            for (int s = 0; s < 2; ++s)
#pragma unroll
                for (int mt = 0; mt < 2; ++mt)
                    ldx4(afr[s][mt], Ab + s*16384 +
                         (uint32_t)SWZ((a_row + mt*16)*128 + ks*32 + a_kb));
#pragma unroll
            for (int nt = 0; nt < 2; ++nt) {
                uint32_t bfr[2][4];
#pragma unroll
                for (int s = 0; s < 2; ++s)
                    ldx4(bfr[s], Bb + s*8192 +
                         (uint32_t)SWZ((b_row + nt*16)*128 + ks*32 + b_kb));
#pragma unroll
                for (int p = 0; p < 3; ++p) {
                    const int s = SA[p], t = SB[p];
#pragma unroll
                    for (int mt = 0; mt < 2; ++mt) {
                        mma16816(&acc[mt][nt][0], afr[s][mt], bfr[t][0], bfr[t][1]);
                        mma16816(&acc[mt][nt][4], afr[s][mt], bfr[t][2], bfr[t][3]);
                    }
                }
            }
        }
        __syncthreads();
    }

    // epilogue: bias + relu -> g_h [n][oc][y][x]
#pragma unroll
    for (int mt = 0; mt < 2; ++mt) {
        const int pix0 = mtile*128 + wm*32 + mt*16 + (lane >> 2);
#pragma unroll
        for (int nt = 0; nt < 2; ++nt) {
#pragma unroll
            for (int h8 = 0; h8 < 2; ++h8) {
                const int oc = ntile*64 + wn*32 + nt*16 + h8*8 + (lane & 3)*2;
                const float b0 = __ldg(bias + oc), b1 = __ldg(bias + oc + 1);
#pragma unroll
                for (int rr = 0; rr < 2; ++rr) {
                    const int pix = pix0 + rr*8;
                    const int y = pix >> 6, xw = pix & 63;
                    float v0 = acc[mt][nt][h8*4 + rr*2 + 0] + b0;
                    float v1 = acc[mt][nt][h8*4 + rr*2 + 1] + b1;
                    g_h[(((size_t)n*OC + oc    )*64 + y)*64 + xw] = fmaxf(v0, 0.f);
                    g_h[(((size_t)n*OC + oc + 1)*64 + y)*64 + xw] = fmaxf(v1, 0.f);
                }
            }
        }
    }
}

// ================= K2: approx 1x1 convs =================
__global__ __launch_bounds__(256) void conv1x1_kernel(
    const float* __restrict__ sw, const float* __restrict__ sb,
    const float* __restrict__ lw, const float* __restrict__ lb, int n0)
{
    const int n = n0 + blockIdx.y;
    const int y = blockIdx.x;
    const int tid = threadIdx.x;
    const int xcol = tid & 63;
    const int cg = tid >> 6;

    __shared__ float hs[64][64];
    __shared__ float wsc[56][64];

    float acc[14];
#pragma unroll
    for (int j = 0; j < 14; ++j) acc[j] = 0.f;

    for (int c0 = 0; c0 < CIN; c0 += 64) {
        for (int idx = tid; idx < 64*64; idx += 256) {
            int ic = idx >> 6, xx = idx & 63;
            hs[ic][xx] = g_h[(((size_t)n*OC + c0 + ic)*HH + y)*WW + xx];
        }
        for (int idx = tid; idx < 56*64; idx += 256) {
            int c = idx >> 6, ic = idx & 63;
            float v = 0.f;
            if (c < 18) v = sw[(size_t)c*CIN + c0 + ic];
            else if (c < 54) v = lw[(size_t)(c-18)*CIN + c0 + ic];
            wsc[c][ic] = v;
        }
        __syncthreads();
#pragma unroll 8
        for (int ic = 0; ic < 64; ++ic) {
            float xv = hs[ic][xcol];
#pragma unroll
            for (int j = 0; j < 14; ++j)
                acc[j] = fmaf(wsc[cg + 4*j][ic], xv, acc[j]);
        }
        __syncthreads();
    }
    int p = y * WW + xcol;
#pragma unroll
    for (int j = 0; j < 14; ++j) {
        int c = cg + 4*j;
        if (c < 18)       g_score[((size_t)n*18 + c)*4096 + p] = acc[j] + sb[c];
        else if (c < 54)  g_loc[((size_t)n*36 + (c-18))*4096 + p] = acc[j] + lb[c-18];
    }
}

// ================= K3: approx boxes / keys + full outputs =================
__global__ __launch_bounds__(256) void boxes_kernel(float* __restrict__ out, int n0)
{
    const int n = n0 + blockIdx.y;
    const int i = blockIdx.x * 256 + threadIdx.x;
    if (i >= NANC) return;
    const int a  = i % NA;
    const int p  = i / NA;
    const int xx = p % WW;
    const int yy = p / WW;

    float s0 = g_score[((size_t)n*18 + 2*a    )*4096 + p];
    float s1 = g_score[((size_t)n*18 + 2*a + 1)*4096 + p];
    out[OFF_SCORES + ((size_t)n*NANC + i)*2 + 0] = s0;
    out[OFF_SCORES + ((size_t)n*NANC + i)*2 + 1] = s1;

    float l0 = g_loc[((size_t)n*36 + a*4 + 0)*4096 + p];
    float l1 = g_loc[((size_t)n*36 + a*4 + 1)*4096 + p];
    float l2 = g_loc[((size_t)n*36 + a*4 + 2)*4096 + p];
    float l3 = g_loc[((size_t)n*36 + a*4 + 3)*4096 + p];
    out[OFF_LOCS + ((size_t)n*NANC + i)*4 + 0] = l0;
    out[OFF_LOCS + ((size_t)n*NANC + i)*4 + 1] = l1;
    out[OFF_LOCS + ((size_t)n*NANC + i)*4 + 2] = l2;
    out[OFF_LOCS + ((size_t)n*NANC + i)*4 + 3] = l3;

    const double ratios[3] = {0.5, 1.0, 2.0};
    const double scales[3] = {8.0, 16.0, 32.0};
    double hh = (16.0 * scales[a % 3]) * sqrt(ratios[a / 3]);
    double wd = (16.0 * scales[a % 3]) * sqrt(1.0 / ratios[a / 3]);
    float ab0 = (float)(8.0 - hh / 2.0);
    float ab1 = (float)(8.0 - wd / 2.0);
    float ab2 = (float)(8.0 + hh / 2.0);
    float ab3 = (float)(8.0 + wd / 2.0);
    float a0 = ab0 + (float)(yy * 16);
    float a1 = ab1 + (float)(xx * 16);
    float a2 = ab2 + (float)(yy * 16);
    float a3 = ab3 + (float)(xx * 16);
    if (n == 0) {
        out[OFF_ANC + (size_t)i*4 + 0] = a0;
        out[OFF_ANC + (size_t)i*4 + 1] = a1;
        out[OFF_ANC + (size_t)i*4 + 2] = a2;
        out[OFF_ANC + (size_t)i*4 + 3] = a3;
    }

    float ha = __fadd_rn(a2, -a0);
    float wa = __fadd_rn(a3, -a1);
    float cy = __fadd_rn(a0, __fmul_rn(0.5f, ha));
    float cx = __fadd_rn(a1, __fmul_rn(0.5f, wa));
    float cy2 = __fadd_rn(__fmul_rn(l0, ha), cy);
    float cx2 = __fadd_rn(__fmul_rn(l1, wa), cx);
    float h2 = __fmul_rn(expf(l2), ha);
    float w2 = __fmul_rn(expf(l3), wa);
    float b0 = __fadd_rn(cy2, -__fmul_rn(0.5f, h2));
    float b1 = __fadd_rn(cx2, -__fmul_rn(0.5f, w2));
    float b2 = __fadd_rn(cy2,  __fmul_rn(0.5f, h2));
    float b3 = __fadd_rn(cx2,  __fmul_rn(0.5f, w2));
    b0 = fminf(fmaxf(b0, 0.f), 1024.f);
    b1 = fminf(fmaxf(b1, 0.f), 1024.f);
    b2 = fminf(fmaxf(b2, 0.f), 1024.f);
    b3 = fminf(fmaxf(b3, 0.f), 1024.f);
    bool valid = ((b2 - b0) >= 16.f) && ((b3 - b1) >= 16.f);

    float m = fmaxf(s0, s1);
    float e0 = expf(s0 - m), e1 = expf(s1 - m);
    float fg = e1 / (e0 + e1);
    if (!valid) fg = -INFINITY;

    float* bp = g_boxes + ((size_t)n*NANC + i)*4;
    bp[0] = b0; bp[1] = b1; bp[2] = b2; bp[3] = b3;

    unsigned int kb = __float_as_uint(fg);
    unsigned int k  = (kb & 0x80000000u) ? ~kb : (kb | 0x80000000u);
    g_key[(size_t)n*NANC + i] =
        ((unsigned long long)k << 16) | (unsigned long long)(65535 - i);
}

// ================= K4: candidate selection (threshold + pixel compaction) =================
__global__ __launch_bounds__(1024) void cand_kernel(int n0)
{
    const int n = n0 + blockIdx.x;
    const int tid = threadIdx.x;
    const int lane = tid & 31, wid = tid >> 5;
    __shared__ unsigned int hist[256];
    __shared__ unsigned long long s_prefix;
    __shared__ int s_rank;
    __shared__ unsigned char flag[4096];
    __shared__ int wsum[32];

    const unsigned long long* key = g_key + (size_t)n * NANC;
    if (tid == 0) { s_prefix = 0ULL; s_rank = CAND_RANK; }
    __syncthreads();

    for (int d = 5; d >= 0; --d) {
        if (tid < 256) hist[tid] = 0u;
        __syncthreads();
        unsigned long long pref = s_prefix;
        int sh = (d + 1) * 8;
        for (int idx = tid; idx < NANC; idx += 1024) {
            unsigned long long k = key[idx];
            if ((k >> sh) == (pref >> sh))
                atomicAdd(&hist[(unsigned)(k >> (8*d)) & 255u], 1u);
        }
        __syncthreads();
        if (tid == 0) {
            int cum = 0, rank = s_rank;
            for (int v = 255; v >= 0; --v) {
                int c = (int)hist[v];
                if (cum + c > rank) {
                    s_prefix = pref | ((unsigned long long)(unsigned)v << (8*d));
                    s_rank = rank - cum;
                    break;
                }
                cum += c;
            }
        }
        __syncthreads();
    }
    const unsigned long long T = s_prefix;
    if (tid == 0) g_tcand[n] = T;

    for (int p = tid; p < 4096; p += 1024) flag[p] = 0;
    __syncthreads();
    for (int i = tid; i < NANC; i += 1024)
        if (key[i] >= T) flag[i / 9] = 1;
    __syncthreads();

    int have[4], cnt = 0;
#pragma unroll
    for (int j = 0; j < 4; ++j) { have[j] = flag[tid*4 + j]; cnt += have[j]; }
    int incl = cnt;
#pragma unroll
    for (int off = 1; off < 32; off <<= 1) {
        int v = __shfl_up_sync(0xffffffffu, incl, off);
        if (lane >= off) incl += v;
    }
    if (lane == 31) wsum[wid] = incl;
    __syncthreads();
    if (wid == 0) {
        int v = wsum[lane];
        int inc2 = v;
#pragma unroll
        for (int off = 1; off < 32; off <<= 1) {
            int u = __shfl_up_sync(0xffffffffu, inc2, off);
            if (lane >= off) inc2 += u;
        }
        wsum[lane] = inc2 - v;   // exclusive
    }
    __syncthreads();
    int base = wsum[wid] + (incl - cnt);
    int run = 0;
#pragma unroll
    for (int j = 0; j < 4; ++j) {
        int p = tid*4 + j;
        if (have[j]) {
            int s = base + run; run++;
            g_plist[n*4096 + s] = (unsigned short)p;
            g_pixslot[n*4096 + p] = (short)s;
        } else {
            g_pixslot[n*4096 + p] = -1;
        }
    }
    if (tid == 1023) g_npx[n] = base + cnt;
}

// ================= K5: gather candidate im2col x in R3 k-order [n][k][slot] =================
__global__ __launch_bounds__(256) void gather_kernel(const float* __restrict__ x, int n0)
{
    const int n = n0 + blockIdx.y, k = blockIdx.x;
    const int cc = k / 72, r = k % 72, ici = r / 9, tap = r % 9;
    const int ky = tap / 3, kx = tap % 3, ch = cc*8 + ici;
    const int npx = g_npx[n];
    int lim = (npx + RS_PX - 1) & ~(RS_PX - 1);
    if (lim > CAND_MAX) lim = CAND_MAX;
    for (int s = threadIdx.x; s < lim; s += 256) {
        float v = 0.f;
        if (s < npx) {
            int pix = g_plist[n*4096 + s];
            int y = pix >> 6, xx = pix & 63;
            int yi = y + ky - 1, xi = xx + kx - 1;
            if ((unsigned)yi < 64u && (unsigned)xi < 64u)
                v = x[(((size_t)n*512 + ch)*64 + yi)*64 + xi];
        }
        g_gather[((size_t)n*KTOT + k)*CAND_MAX + s] = v;
    }
}

// ================= K6: exact rescore GEMM — bit-exact R3 fmaf chains (R13 shape) =================
__global__ void __launch_bounds__(256, 2) rescore_gemm_kernel(const float* __restrict__ bias, int n0)
{
    __shared__ float xs[2][32][64];
    __shared__ float ws[2][32][64];
    const int sblk = blockIdx.x, ob = blockIdx.y, n = n0 + blockIdx.z;
    if (sblk * RS_PX >= g_npx[n]) return;
    const int tid = threadIdx.x;
    const int pq = tid & 15, oq = tid >> 4;
    const size_t gbase = (size_t)n*KTOT*CAND_MAX + (size_t)sblk*RS_PX;

    float acc[4][4];
#pragma unroll
    for (int i = 0; i < 4; ++i)
#pragma unroll
        for (int j = 0; j < 4; ++j) acc[i][j] = 0.f;

#pragma unroll
    for (int q = 0; q < 2; ++q) {
        int f = tid + q*256, row = f >> 4, c4 = f & 15;
        *(float4*)&xs[0][row][c4*4] =
            *(const float4*)(g_gather + gbase + (size_t)row*CAND_MAX + c4*4);
        *(float4*)&ws[0][row][c4*4] =
            *(const float4*)(g_wg + (size_t)row*512 + ob*64 + c4*4);
    }
    __syncthreads();
    int buf = 0;

    for (int kt = 0; kt < 144; ++kt) {
        float4 rx[2], rw[2];
        if (kt < 143) {
            const int k1 = (kt + 1) * 32;
#pragma unroll
            for (int q = 0; q < 2; ++q) {
                int f = tid + q*256, row = f >> 4, c4 = f & 15;
                rx[q] = *(const float4*)(g_gather + gbase + (size_t)(k1 + row)*CAND_MAX + c4*4);
                rw[q] = *(const float4*)(g_wg + (size_t)(k1 + row)*512 + ob*64 + c4*4);
            }
        }
#pragma unroll
        for (int kk = 0; kk < 32; ++kk) {
            float4 xv = *(float4*)&xs[buf][kk][pq*4];
            float4 wv = *(float4*)&ws[buf][kk][oq*4];
            float xa[4] = {xv.x, xv.y, xv.z, xv.w};
            float wa[4] = {wv.x, wv.y, wv.z, wv.w};
#pragma unroll
            for (int i = 0; i < 4; ++i)
#pragma unroll
                for (int j = 0; j < 4; ++j)
                    acc[i][j] = __fmaf_rn(wa[j], xa[i], acc[i][j]);
        }
        if (kt < 143) {
            __syncthreads();
#pragma unroll
            for (int q = 0; q < 2; ++q) {
                int f = tid + q*256, row = f >> 4, c4 = f & 15;
                *(float4*)&xs[buf ^ 1][row][c4*4] = rx[q];
                *(float4*)&ws[buf ^ 1][row][c4*4] = rw[q];
            }
            __syncthreads();
            buf ^= 1;
        }
    }

    float bv[4];
#pragma unroll
    for (int j = 0; j < 4; ++j) bv[j] = __ldg(bias + ob*64 + oq*4 + j);
#pragma unroll
    for (int i = 0; i < 4; ++i) {
        int slot = sblk*RS_PX + pq*4 + i;
        float4 o;
        o.x = fmaxf(__fadd_rn(acc[i][0], bv[0]), 0.f);
        o.y = fmaxf(__fadd_rn(acc[i][1], bv[1]), 0.f);
        o.z = fmaxf(__fadd_rn(acc[i][2], bv[2]), 0.f);
        o.w = fmaxf(__fadd_rn(acc[i][3], bv[3]), 0.f);
        *(float4*)(g_hex + ((size_t)n*CAND_MAX + slot)*512 + ob*64 + oq*4) = o;
    }
}

// ================= K7: exact per-anchor score/loc/key/box (R3 conv1x1 order) =================
__global__ __launch_bounds__(256) void rescore_anchor_kernel(
    const float* __restrict__ sw, const float* __restrict__ sb,
    const float* __restrict__ lw, const float* __restrict__ lb, int n0)
{
    const int n = n0 + blockIdx.y;
    const int i = blockIdx.x * 256 + threadIdx.x;
    if (i >= NANC) return;
    if (g_key[(size_t)n*NANC + i] < g_tcand[n]) return;
    const int a = i % NA, p = i / NA;
    const int slot = g_pixslot[n*4096 + p];
    if (slot < 0) return;
    const float* h = g_hex + ((size_t)n*CAND_MAX + slot)*512;
    const float* w0 = sw + (size_t)(2*a)*512;
    const float* w1 = sw + (size_t)(2*a + 1)*512;
    const float* wl0 = lw + (size_t)(4*a + 0)*512;
    const float* wl1 = lw + (size_t)(4*a + 1)*512;
    const float* wl2 = lw + (size_t)(4*a + 2)*512;
    const float* wl3 = lw + (size_t)(4*a + 3)*512;

    float s0 = 0.f, s1 = 0.f, l0 = 0.f, l1 = 0.f, l2 = 0.f, l3 = 0.f;
    for (int ic = 0; ic < 512; ic += 4) {
        float4 hv = *(const float4*)(h + ic);
        float ha[4] = {hv.x, hv.y, hv.z, hv.w};
#pragma unroll
        for (int q = 0; q < 4; ++q) {
            float hq = ha[q];
            s0 = __fmaf_rn(__ldg(w0 + ic + q), hq, s0);
            s1 = __fmaf_rn(__ldg(w1 + ic + q), hq, s1);
            l0 = __fmaf_rn(__ldg(wl0 + ic + q), hq, l0);
            l1 = __fmaf_rn(__ldg(wl1 + ic + q), hq, l1);
            l2 = __fmaf_rn(__ldg(wl2 + ic + q), hq, l2);
            l3 = __fmaf_rn(__ldg(wl3 + ic + q), hq, l3);
        }
    }
    s0 = __fadd_rn(s0, __ldg(sb + 2*a));
    s1 = __fadd_rn(s1, __ldg(sb + 2*a + 1));
    l0 = __fadd_rn(l0, __ldg(lb + 4*a + 0));
    l1 = __fadd_rn(l1, __ldg(lb + 4*a + 1));
    l2 = __fadd_rn(l2, __ldg(lb + 4*a + 2));
    l3 = __fadd_rn(l3, __ldg(lb + 4*a + 3));

    const int xx = p % WW, yy = p / WW;
    const double ratios[3] = {0.5, 1.0, 2.0};
    const double scales[3] = {8.0, 16.0, 32.0};
    double hh = (16.0 * scales[a % 3]) * sqrt(ratios[a / 3]);
    double wd = (16.0 * scales[a % 3]) * sqrt(1.0 / ratios[a / 3]);
    float a0 = (float)(8.0 - hh / 2.0) + (float)(yy * 16);
    float a1 = (float)(8.0 - wd / 2.0) + (float)(xx * 16);
    float a2 = (float)(8.0 + hh / 2.0) + (float)(yy * 16);
    float a3 = (float)(8.0 + wd / 2.0) + (float)(xx * 16);

    float haa = __fadd_rn(a2, -a0);
    float waa = __fadd_rn(a3, -a1);
    float cy = __fadd_rn(a0, __fmul_rn(0.5f, haa));
    float cx = __fadd_rn(a1, __fmul_rn(0.5f, waa));
    float cy2 = __fadd_rn(__fmul_rn(l0, haa), cy);
    float cx2 = __fadd_rn(__fmul_rn(l1, waa), cx);
    float h2 = __fmul_rn(expf(l2), haa);
    float w2 = __fmul_rn(expf(l3), waa);
    float b0 = __fadd_rn(cy2, -__fmul_rn(0.5f, h2));
    float b1 = __fadd_rn(cx2, -__fmul_rn(0.5f, w2));
    float b2 = __fadd_rn(cy2,  __fmul_rn(0.5f, h2));
    float b3 = __fadd_rn(cx2,  __fmul_rn(0.5f, w2));
    b0 = fminf(fmaxf(b0, 0.f), 1024.f);
    b1 = fminf(fmaxf(b1, 0.f), 1024.f);
    b2 = fminf(fmaxf(b2, 0.f), 1024.f);
    b3 = fminf(fmaxf(b3, 0.f), 1024.f);
    bool valid = ((b2 - b0) >= 16.f) && ((b3 - b1) >= 16.f);

    float m = fmaxf(s0, s1);
    float e0 = expf(s0 - m), e1 = expf(s1 - m);
    float fg = e1 / (e0 + e1);
    if (!valid) fg = -INFINITY;

    float* bp = g_boxes + ((size_t)n*NANC + i)*4;
    bp[0] = b0; bp[1] = b1; bp[2] = b2; bp[3] = b3;

    unsigned int kb = __float_as_uint(fg);
    unsigned int k  = (kb & 0x80000000u) ? ~kb : (kb | 0x80000000u);
    g_key[(size_t)n*NANC + i] =
        ((unsigned long long)k << 16) | (unsigned long long)(65535 - i);
}

// ================= K8: exact top-2000 =================
__global__ __launch_bounds__(1024) void topk_kernel(int n0)
{
    const int n = n0 + blockIdx.x;
    const int tid = threadIdx.x;
    __shared__ unsigned int hist[256];
    __shared__ unsigned long long ssort[2048];
    __shared__ unsigned long long s_prefix;
    __shared__ int s_rank;
    __shared__ int s_cnt;

    const unsigned long long* key = g_key + (size_t)n * NANC;
    if (tid == 0) { s_prefix = 0ULL; s_rank = PRE_NMS - 1; s_cnt = 0; }
    if (tid < 32) g_keep0[n*32 + tid] = 0ULL;
    __syncthreads();

    for (int d = 5; d >= 0; --d) {
        if (tid < 256) hist[tid] = 0u;
        __syncthreads();
        unsigned long long pref = s_prefix;
        int sh = (d + 1) * 8;
        for (int idx = tid; idx < NANC; idx += 1024) {
            unsigned long long k = key[idx];
            if ((k >> sh) == (pref >> sh))
                atomicAdd(&hist[(unsigned)(k >> (8*d)) & 255u], 1u);
        }
        __syncthreads();
        if (tid == 0) {
            int cum = 0, rank = s_rank;
            for (int v = 255; v >= 0; --v) {
                int c = (int)hist[v];
                if (cum + c > rank) {
                    s_prefix = pref | ((unsigned long long)(unsigned)v << (8*d));
                    s_rank = rank - cum;
                    break;
                }
                cum += c;
            }
        }
        __syncthreads();
    }
    unsigned long long T = s_prefix;
    __syncthreads();
    for (int idx = tid; idx < NANC; idx += 1024) {
        unsigned long long k = key[idx];
        if (k >= T) {
            int pos = atomicAdd(&s_cnt, 1);
            if (pos < 2048) ssort[pos] = k;
        }
    }
    __syncthreads();
    int cnt = s_cnt;
    for (int idx = cnt + tid; idx < 2048; idx += 1024) ssort[idx] = 0ULL;
    __syncthreads();

    for (int ksz = 2; ksz <= 2048; ksz <<= 1) {
        for (int j = ksz >> 1; j > 0; j >>= 1) {
            for (int idx = tid; idx < 2048; idx += 1024) {
                int ixj = idx ^ j;
                if (ixj > idx) {
                    unsigned long long va = ssort[idx], vb = ssort[ixj];
                    bool desc = ((idx & ksz) == 0);
                    if (desc ? (va < vb) : (va > vb)) { ssort[idx] = vb; ssort[ixj] = va; }
                }
            }
            __syncthreads();
        }
    }

    for (int r = tid; r < PRE_NMS; r += 1024) {
        unsigned long long comp = ssort[r];
        int idx = 65535 - (int)(comp & 0xFFFFULL);
        const float4 bv = *reinterpret_cast<const float4*>(g_boxes + ((size_t)n*NANC + idx)*4);
        *reinterpret_cast<float4*>(g_selbox + ((size_t)n*PRE_NMS + r)*4) = bv;
        unsigned int fk = (unsigned)(comp >> 16);
        if (fk > 0x007FFFFFu)
            atomicOr(&g_keep0[n*32 + (r >> 6)], 1ULL << (r & 63));
    }
}

// ================= K9: NMS mask =================
__global__ __launch_bounds__(512) void nms_mask_kernel(int n0)
{
    const int n = n0 + blockIdx.y;
    const int i = blockIdx.x * 16 + threadIdx.y;
    const int t = threadIdx.x;
    __shared__ float4 bj[PRE_NMS];
    int ftid = threadIdx.y * 32 + threadIdx.x;
    for (int idx = ftid; idx < PRE_NMS; idx += 512)
        bj[idx] = *reinterpret_cast<const float4*>(g_selbox + ((size_t)n*PRE_NMS + idx)*4);
    __syncthreads();

    float4 bi = bj[i];
    float ai = (bi.z - bi.x) * (bi.w - bi.y);
    unsigned long long bits = 0ULL;
    int jbase = t << 6;
#pragma unroll 4
    for (int jj = 0; jj < 64; ++jj) {
        int j = jbase + jj;
        if (j >= PRE_NMS) break;
        if (j <= i) continue;
        float4 b = bj[j];
        float aj = (b.z - b.x) * (b.w - b.y);
        float ty = fmaxf(bi.x, b.x), tx = fmaxf(bi.y, b.y);
        float by = fminf(bi.z, b.z), bx = fminf(bi.w, b.w);
        float ih = fmaxf(by - ty, 0.f), iw = fmaxf(bx - tx, 0.f);
        float inter = ih * iw;
        float iou = inter / (ai + aj - inter + 1e-9f);
        if (iou > 0.7f) bits |= (1ULL << jj);
    }
    g_mask[((size_t)n*PRE_NMS + i)*32 + t] = bits;
}

// ================= K10: greedy scan =================
__global__ __launch_bounds__(32) void scan_kernel(float* __restrict__ out, int n0)
{
    const int n = n0 + blockIdx.x;
    const int t = threadIdx.x;
    __shared__ unsigned long long rem[32];
    __shared__ unsigned long long kw[32];
    __shared__ int s_flag;
    rem[t] = 0ULL;
    kw[t] = g_keep0[n*32 + t];
    __syncthreads();

    int cnt = 0;
    for (int r = 0; r < PRE_NMS; ++r) {
        if (t == 0) {
            unsigned long long bit = 1ULL << (r & 63);
            s_flag = ((kw[r >> 6] & bit) != 0ULL && (rem[r >> 6] & bit) == 0ULL) ? 1 : 0;
        }
        __syncthreads();
        int f = s_flag;
        __syncthreads();
        if (f) {
            rem[t] |= g_mask[((size_t)n*PRE_NMS + r)*32 + t];
            if (t < 4)
                out[OFF_ROIS + ((size_t)n*POST_NMS + cnt)*4 + t] =
                    g_selbox[((size_t)n*PRE_NMS + r)*4 + t];
            cnt++;
        }
        __syncthreads();
        if (f && cnt == POST_NMS) break;
    }
    for (int idx = cnt*4 + t; idx < POST_NMS*4; idx += 32)
        out[OFF_ROIS + (size_t)n*POST_NMS*4 + idx] = 0.f;
    for (int idx = t; idx < POST_NMS; idx += 32)
        out[OFF_IND + (size_t)n*POST_NMS + idx] = (float)n;
}

// ================= launch: two-stream split-batch pipeline =================
static void launch_half(cudaStream_t st, int n0,
                        const float* x, const float* b1,
                        const float* sw, const float* sb,
                        const float* lw, const float* lb, float* out)
{
    conv3x3_mma_kernel<<<dim3(32, 8, NBH), 256, SMEM_MMA_TOTAL, st>>>(b1, n0);
    conv1x1_kernel<<<dim3(64, NBH), 256, 0, st>>>(sw, sb, lw, lb, n0);
    boxes_kernel<<<dim3((NANC + 255) / 256, NBH), 256, 0, st>>>(out, n0);
    cand_kernel<<<NBH, 1024, 0, st>>>(n0);
    gather_kernel<<<dim3(KTOT, NBH), 256, 0, st>>>(x, n0);
    rescore_gemm_kernel<<<dim3(CAND_MAX/RS_PX, 8, NBH), 256, 0, st>>>(b1, n0);
    rescore_anchor_kernel<<<dim3((NANC + 255) / 256, NBH), 256, 0, st>>>(sw, sb, lw, lb, n0);
    topk_kernel<<<NBH, 1024, 0, st>>>(n0);
    nms_mask_kernel<<<dim3(PRE_NMS / 16, NBH), dim3(32, 16), 0, st>>>(n0);
    scan_kernel<<<NBH, 32, 0, st>>>(out, n0);
}

extern "C" void kernel_launch(void* const* d_in, const int* in_sizes, int n_in,
                              void* d_out, int out_size)
{
    const float* x  = (const float*)d_in[0];
    const float* w1 = (const float*)d_in[1];
    const float* b1 = (const float*)d_in[2];
    const float* sw = (const float*)d_in[3];
    const float* sb = (const float*)d_in[4];
    const float* lw = (const float*)d_in[5];
    const float* lb = (const float*)d_in[6];
    float* out = (float*)d_out;

    static cudaStream_t s2 = nullptr;
    static cudaEvent_t evP = nullptr, evC = nullptr, evE = nullptr;
    if (s2 == nullptr) {
        cudaStreamCreateWithFlags(&s2, cudaStreamNonBlocking);
        cudaEventCreateWithFlags(&evP, cudaEventDisableTiming);
        cudaEventCreateWithFlags(&evC, cudaEventDisableTiming);
        cudaEventCreateWithFlags(&evE, cudaEventDisableTiming);
        cudaFuncSetAttribute(conv3x3_mma_kernel,
                             cudaFuncAttributeMaxDynamicSharedMemorySize, SMEM_MMA_TOTAL);
    }

    // shared prep + half-0 input split on stream 0
    split_w_kernel<<<512, 512>>>(w1);
    prep_wg_kernel<<<KTOT, 256>>>(w1);
    split_x_kernel<<<dim3(8, 64, NBH), 256>>>(x, 0);
    cudaEventRecord(evP, 0);

    // half 0 chain on stream 0 (conv first, then record stagger event)
    conv3x3_mma_kernel<<<dim3(32, 8, NBH), 256, SMEM_MMA_TOTAL>>>(b1, 0);
    cudaEventRecord(evC, 0);
    conv1x1_kernel<<<dim3(64, NBH), 256>>>(sw, sb, lw, lb, 0);
    boxes_kernel<<<dim3((NANC + 255) / 256, NBH), 256>>>(out, 0);
    cand_kernel<<<NBH, 1024>>>(0);
    gather_kernel<<<dim3(KTOT, NBH), 256>>>(x, 0);
    rescore_gemm_kernel<<<dim3(CAND_MAX/RS_PX, 8, NBH), 256>>>(b1, 0);
    rescore_anchor_kernel<<<dim3((NANC + 255) / 256, NBH), 256>>>(sw, sb, lw, lb, 0);
    topk_kernel<<<NBH, 1024>>>(0);
    nms_mask_kernel<<<dim3(PRE_NMS / 16, NBH), dim3(32, 16)>>>(0);
    scan_kernel<<<NBH, 32>>>(out, 0);

    // half 1 on s2: join capture via event waits, stagger conv after half-0 conv
    cudaStreamWaitEvent(s2, evP, 0);
    split_x_kernel<<<dim3(8, 64, NBH), 256, 0, s2>>>(x, NBH);
    cudaStreamWaitEvent(s2, evC, 0);
    launch_half(s2, NBH, x, b1, sw, sb, lw, lb, out);
    cudaEventRecord(evE, s2);
    cudaStreamWaitEvent(0, evE, 0);
}